// round 9
// baseline (speedup 1.0000x reference)
#include <cuda_runtime.h>
#include <cuda_fp16.h>
#include <stdint.h>
#include <math.h>

#define CH 128
#define NPIX 32768              // 32*32*32
#define NTOT (NPIX*CH)          // 4194304
#define NQ (NTOT/4)
#define WSIZE (3*3*129*128)
#define NWB (9*128*128)         // 147456
#define MAX_STEPS 32
#define GRID 256
#define NTHREADS 128
#define NTILE 256

// ---- Dormand-Prince coefficients ----
#define C10 0.2f
#define C20 ((float)(3.0/40.0))
#define C21 ((float)(9.0/40.0))
#define C30 ((float)(44.0/45.0))
#define C31 ((float)(-56.0/15.0))
#define C32 ((float)(32.0/9.0))
#define C40 ((float)(19372.0/6561.0))
#define C41 ((float)(-25360.0/2187.0))
#define C42 ((float)(64448.0/6561.0))
#define C43 ((float)(-212.0/729.0))
#define C50 ((float)(9017.0/3168.0))
#define C51 ((float)(-355.0/33.0))
#define C52 ((float)(46732.0/5247.0))
#define C53 ((float)(49.0/176.0))
#define C54 ((float)(-5103.0/18656.0))
#define B0c ((float)(35.0/384.0))
#define B2c ((float)(500.0/1113.0))
#define B3c ((float)(125.0/192.0))
#define B4c ((float)(-2187.0/6784.0))
#define B5c ((float)(11.0/84.0))
#define E0c ((float)(35.0/384.0 - 5179.0/57600.0))
#define E2c ((float)(500.0/1113.0 - 7571.0/16695.0))
#define E3c ((float)(125.0/192.0 - 393.0/640.0))
#define E4c ((float)(-2187.0/6784.0 + 92097.0/339200.0))
#define E5c ((float)(11.0/84.0 - 187.0/2100.0))
#define E6c ((float)(-1.0/40.0))

// ---- Persistent state ----
__device__ __align__(16) float g_yf[2][NTOT];        // ping-pong fp32 y ([cur^1] holds y5)
__device__ __align__(16) float g_k[7][NTOT];
__device__ __align__(16) __half g_yh[2][NTOT];       // fp16 mirrors
__device__ __align__(16) __half g_tmph[NTOT];
__device__ __align__(16) __half g_hh[NTOT];
__device__ __align__(16) __half g_wh[2][NWB];        // [conv][tap*16384 + co*128 + ci]
__device__ float g_tw[2][9][128];
__device__ double g_part[NTILE];
__device__ unsigned g_arrive, g_gen;                 // grid barrier (zero-init)

// ---- conv smem: 3-stage ring of {A, W}; rows 128 x (64 fp16 = 128B + 16B pad) ----
#define ROWB 144
#define TILE_B (128*ROWB)        // 18432
#define A_OFF 0
#define W_OFF TILE_B
#define STG   (2*TILE_B)         // 36864
#define CONV_SMEM (3*STG)        // 110592

// ============ PTX wrappers (base ISA, valid for compute_103) ============
__device__ __forceinline__ uint32_t smem_u32(const void* p){
    uint32_t a;
    asm("{ .reg .u64 t; cvta.to.shared.u64 t, %1; cvt.u32.u64 %0, t; }" : "=r"(a) : "l"(p));
    return a;
}
__device__ __forceinline__ void cpa16(uint32_t dst, const void* src, uint32_t sz){
    asm volatile("cp.async.cg.shared.global [%0], [%1], 16, %2;" :: "r"(dst), "l"(src), "r"(sz));
}
#define CP_COMMIT() asm volatile("cp.async.commit_group;" ::: "memory")
#define CP_WAIT1()  asm volatile("cp.async.wait_group 1;" ::: "memory")
#define CP_WAIT0()  asm volatile("cp.async.wait_group 0;" ::: "memory")

__device__ __forceinline__ void ldm4(uint32_t* r, uint32_t addr){
    asm volatile("ldmatrix.sync.aligned.m8n8.x4.shared.b16 {%0,%1,%2,%3}, [%4];"
        : "=r"(r[0]), "=r"(r[1]), "=r"(r[2]), "=r"(r[3]) : "r"(addr));
}
__device__ __forceinline__ void mma16816(float* c, const uint32_t* a, uint32_t b0, uint32_t b1){
    asm volatile("mma.sync.aligned.m16n8k16.row.col.f32.f16.f16.f32 "
        "{%0,%1,%2,%3}, {%4,%5,%6,%7}, {%8,%9}, {%0,%1,%2,%3};"
        : "+f"(c[0]), "+f"(c[1]), "+f"(c[2]), "+f"(c[3])
        : "r"(a[0]), "r"(a[1]), "r"(a[2]), "r"(a[3]), "r"(b0), "r"(b1));
}
__device__ __forceinline__ uint32_t pk2h(__half a, __half b){
    return (uint32_t)__half_as_ushort(a) | ((uint32_t)__half_as_ushort(b) << 16);
}
__device__ __forceinline__ void h_store4(__half* Hp, int e, float4 v){
    uint2 H = make_uint2(pk2h(__float2half(v.x), __float2half(v.y)),
                         pk2h(__float2half(v.z), __float2half(v.w)));
    *(uint2*)(Hp + e) = H;
}

// ---- grid-wide sense barrier (all GRID CTAs resident) ----
__device__ __forceinline__ void gsync(){
    __threadfence();
    __syncthreads();
    if (threadIdx.x == 0){
        unsigned g;
        asm volatile("ld.acquire.gpu.u32 %0, [%1];" : "=r"(g) : "l"(&g_gen));
        unsigned old;
        asm volatile("atom.add.release.gpu.u32 %0, [%1], 1;" : "=r"(old) : "l"(&g_arrive) : "memory");
        if (old == GRID-1){
            asm volatile("st.relaxed.gpu.u32 [%0], 0;" :: "l"(&g_arrive) : "memory");
            asm volatile("st.release.gpu.u32 [%0], %1;" :: "l"(&g_gen), "r"(g+1) : "memory");
        } else {
            unsigned cur;
            do {
                __nanosleep(64);
                asm volatile("ld.acquire.gpu.u32 %0, [%1];" : "=r"(cur) : "l"(&g_gen));
            } while (cur == g);
        }
    }
    __syncthreads();
}

#define LDK(j) __ldcg((const float2*)(g_k[j]+idx))

// ============ conv phase: CTA tile 128pix x 128co; 4 warps, warp tile 64x64 ============
template<int WSEL>
__device__ __forceinline__ void conv_phase(
    uint32_t sb, int tile, int s,
    const float* __restrict__ Bias, float dtc, float tval, int cur,
    double* sdErr)
{
    const int tid  = threadIdx.x;
    const int wid  = tid >> 5;
    const int lane = tid & 31;

    const __half* __restrict__ X = (WSEL==0) ? ((s==0) ? g_yh[cur] : g_tmph) : g_hh;
    const __half* __restrict__ Wg = g_wh[WSEL];

    // warp tile origin: 2x2 arrangement of 64x64 tiles
    const int m0 = (wid & 1) * 64;
    const int n0 = (wid >> 1) * 64;
    const uint32_t aoffbase = (uint32_t)((m0 + (lane & 15))*ROWB + (lane >> 4)*16);
    const uint32_t boffbase = (uint32_t)((n0 + (lane & 7) + ((lane >> 4) << 3))*ROWB + ((lane >> 3) & 1)*16);

    float acc[4][8][4];
    #pragma unroll
    for (int i=0;i<4;i++)
        #pragma unroll
        for (int j=0;j<8;j++)
            #pragma unroll
            for (int q=0;q<4;q++) acc[i][j][q]=0.f;

    const int rowbase = tid >> 3;
    const int seg = tid & 7;          // 8-element (16B) segment within 64-ci row
    const int mglob = tile*128;

    auto load_chunk = [&](int c, int st){
        const int tap = c >> 1, ci0 = (c & 1) << 6;
        const int dh = tap/3 - 1, dw = tap - (tap/3)*3 - 1;
        const uint32_t base = sb + st*STG;
        const int wbase = tap*16384 + ci0 + seg*8;
        #pragma unroll
        for (int j=0;j<8;j++){
            int row = rowbase + j*16;
            int m = mglob + row;
            int n = (m >> 10) << 10;
            int hp = (m >> 5) & 31, wp = m & 31;
            int hs = hp + dh, ws = wp + dw;
            bool v = ((unsigned)hs < 32u) && ((unsigned)ws < 32u);
            long off = v ? (((long)(n + hs*32 + ws)) << 7) + ci0 + seg*8 : 0;
            uint32_t dA = base + (uint32_t)(row*ROWB + seg*16);
            cpa16(dA + A_OFF, X + off, v ? 16u : 0u);
            cpa16(dA + W_OFF, Wg + (wbase + row*128), 16u);
        }
    };

    load_chunk(0,0); CP_COMMIT();
    load_chunk(1,1); CP_COMMIT();

    #pragma unroll 1
    for (int c=0; c<18; ++c){
        if (c==17) CP_WAIT0(); else CP_WAIT1();
        __syncthreads();
        if (c<16){ load_chunk(c+2, (c+2)%3); CP_COMMIT(); }

        const uint32_t cb = sb + (c%3)*STG;
        const uint32_t aoff = cb + A_OFF + aoffbase;
        const uint32_t boff = cb + W_OFF + boffbase;
        #pragma unroll
        for (int k16=0; k16<4; ++k16){
            const uint32_t kb = (uint32_t)(k16*32);
            uint32_t a[4][4], b[4][4];
            #pragma unroll
            for (int mt=0;mt<4;mt++) ldm4(a[mt], aoff + (uint32_t)(mt*16*ROWB) + kb);
            #pragma unroll
            for (int nt=0;nt<4;nt++) ldm4(b[nt], boff + (uint32_t)(nt*16*ROWB) + kb);
            #pragma unroll
            for (int mt=0;mt<4;mt++)
                #pragma unroll
                for (int nt=0;nt<4;nt++){
                    mma16816(acc[mt][2*nt],   a[mt], b[nt][0], b[nt][1]);
                    mma16816(acc[mt][2*nt+1], a[mt], b[nt][2], b[nt][3]);
                }
        }
    }

    // ---- epilogue ----
    const int gID = lane >> 2, tq = lane & 3;
    double errsum = 0.0;
    #pragma unroll
    for (int mt=0; mt<4; ++mt){
        #pragma unroll
        for (int rr=0; rr<2; ++rr){
            int r = m0 + mt*16 + rr*8 + gID;
            int m = mglob + r;
            int hp = (m >> 5) & 31, wp = m & 31;
            int cat = ((hp==0)?0:(hp==31)?6:3) + ((wp==0)?0:(wp==31)?2:1);
            const float* tw = g_tw[WSEL][cat];
            #pragma unroll
            for (int nf=0; nf<8; ++nf){
                int col = n0 + nf*8 + tq*2;
                float v0 = fmaxf(acc[mt][nf][rr*2+0] + tval*tw[col]   + Bias[col],   0.f);
                float v1 = fmaxf(acc[mt][nf][rr*2+1] + tval*tw[col+1] + Bias[col+1], 0.f);
                int idx = m*128 + col;
                if (WSEL==0){
                    *(uint32_t*)(g_hh + idx) = pk2h(__float2half(v0), __float2half(v1));
                } else {
                    *(float2*)(g_k[s] + idx) = make_float2(v0, v1);
                    if (s <= 5){
                        float2 y = __ldcg((const float2*)(g_yf[cur] + idx));
                        float c0, c1;
                        if (s==0){ c0 = C10*v0; c1 = C10*v1; }
                        else if (s==1){
                            float2 k0=LDK(0);
                            c0 = C20*k0.x + C21*v0; c1 = C20*k0.y + C21*v1;
                        } else if (s==2){
                            float2 k0=LDK(0), k1=LDK(1);
                            c0 = C30*k0.x + C31*k1.x + C32*v0;
                            c1 = C30*k0.y + C31*k1.y + C32*v1;
                        } else if (s==3){
                            float2 k0=LDK(0), k1=LDK(1), k2=LDK(2);
                            c0 = C40*k0.x + C41*k1.x + C42*k2.x + C43*v0;
                            c1 = C40*k0.y + C41*k1.y + C42*k2.y + C43*v1;
                        } else if (s==4){
                            float2 k0=LDK(0), k1=LDK(1), k2=LDK(2), k3=LDK(3);
                            c0 = C50*k0.x + C51*k1.x + C52*k2.x + C53*k3.x + C54*v0;
                            c1 = C50*k0.y + C51*k1.y + C52*k2.y + C53*k3.y + C54*v1;
                        } else {
                            float2 k0=LDK(0), k2=LDK(2), k3=LDK(3), k4=LDK(4);
                            c0 = B0c*k0.x + B2c*k2.x + B3c*k3.x + B4c*k4.x + B5c*v0;
                            c1 = B0c*k0.y + B2c*k2.y + B3c*k3.y + B4c*k4.y + B5c*v1;
                        }
                        float t0 = y.x + dtc*c0, t1 = y.y + dtc*c1;
                        uint32_t pk = pk2h(__float2half(t0), __float2half(t1));
                        *(uint32_t*)(g_tmph + idx) = pk;
                        if (s==5){
                            *(float2*)(g_yf[cur^1] + idx) = make_float2(t0, t1);
                            *(uint32_t*)(g_yh[cur^1] + idx) = pk;
                        }
                    } else {
                        float2 k0=LDK(0), k2=LDK(2), k3=LDK(3), k4=LDK(4), k5=LDK(5);
                        float2 y  = __ldcg((const float2*)(g_yf[cur]   + idx));
                        float2 y5 = __ldcg((const float2*)(g_yf[cur^1] + idx));
                        float e0 = dtc*(E0c*k0.x + E2c*k2.x + E3c*k3.x + E4c*k4.x + E5c*k5.x + E6c*v0);
                        float e1 = dtc*(E0c*k0.y + E2c*k2.y + E3c*k3.y + E4c*k4.y + E5c*k5.y + E6c*v1);
                        float sc0 = 1e-3f + 1e-3f*fmaxf(fabsf(y.x), fabsf(y5.x));
                        float sc1 = 1e-3f + 1e-3f*fmaxf(fabsf(y.y), fabsf(y5.y));
                        float r0 = e0/sc0, r1 = e1/sc1;
                        errsum += (double)r0*(double)r0 + (double)r1*(double)r1;
                    }
                }
            }
        }
    }
    if (WSEL==1 && s==6){
        sdErr[tid] = errsum;
        __syncthreads();
        for (int o=64; o>0; o>>=1){
            if (tid < o) sdErr[tid] += sdErr[tid+o];
            __syncthreads();
        }
        __syncthreads();
        if (tid==0) g_part[tile] = sdErr[0];
    }
}

// ============ the single persistent kernel ============
__global__ __launch_bounds__(NTHREADS,2)
void k_solver(const float* __restrict__ x,
              const float* __restrict__ w1, const float* __restrict__ b1,
              const float* __restrict__ w2, const float* __restrict__ b2,
              float* __restrict__ out)
{
    extern __shared__ __align__(16) char dsm[];
    __shared__ double sd[NTHREADS];
    const uint32_t sb = smem_u32(dsm);
    const int bid = blockIdx.x, tid = threadIdx.x;
    const int gt = bid*NTHREADS + tid;
    const int gstride = GRID*NTHREADS;

    // ---- prep: weights (transposed fp16) ----
    for (int i=gt; i<2*NWB; i+=gstride){
        int conv = i / NWB, r = i % NWB;
        int tap = r >> 14, co = (r >> 7) & 127, ci = r & 127;
        float v = (conv ? w2 : w1)[(tap*129 + ci)*128 + co];
        g_wh[conv][r] = __float2half(v);
    }
    // ---- prep: t-channel weight sums per border category ----
    if (bid < 2){
        int conv = bid, co = tid;
        const float* w = conv ? w2 : w1;
        for (int cat=0; cat<9; cat++){
            int hc = cat/3, wc = cat%3;
            float ssum = 0.f;
            for (int tap=0; tap<9; tap++){
                int dh = tap/3 - 1, dw = tap%3 - 1;
                bool okh = !((hc==0 && dh<0) || (hc==2 && dh>0));
                bool okw = !((wc==0 && dw<0) || (wc==2 && dw>0));
                if (okh && okw) ssum += w[(tap*129 + 128)*128 + co];
            }
            g_tw[conv][cat][co] = ssum;
        }
    }
    // ---- init y ----
    for (int q=gt; q<NQ; q+=gstride){
        float4 v = ((const float4*)x)[q];
        ((float4*)g_yf[0])[q] = v;
        h_store4(g_yh[0], q*4, v);
    }
    gsync();

    // ---- per-CTA solver state (identical in every CTA) ----
    float t = 0.f, dt = 0.05f;
    int cur = 0, done = 0;
    const float TC[7] = {0.f, 0.2f, 0.3f, 0.8f, (float)(8.0/9.0), 1.f, 1.f};

    for (int it=0; it<MAX_STEPS; ++it){
        if (done) break;
        const float dtc = fminf(dt, 1.0f - t);
        for (int s=0; s<7; ++s){
            const float tval = t + TC[s]*dtc;
            conv_phase<0>(sb, bid, s, b1, dtc, tval, cur, sd);   // h
            gsync();
            conv_phase<1>(sb, bid, s, b2, dtc, tval, cur, sd);   // k_s (+fused)
            gsync();
        }
        // ---- controller, computed redundantly & identically in every CTA ----
        {
            double v=0.0;
            for (int i=tid; i<NTILE; i+=NTHREADS) v += __ldcg(&g_part[i]);
            sd[tid]=v; __syncthreads();
            for (int o=64; o>0; o>>=1){ if (tid<o) sd[tid]+=sd[tid+o]; __syncthreads(); }
            float err_norm = sqrtf((float)(sd[0] / (double)NTOT));
            __syncthreads();
            err_norm = fmaxf(err_norm, 1e-10f);
            int accept = (err_norm <= 1.0f) ? 1 : 0;
            float factor = 0.9f * powf(err_norm, -0.2f);
            factor = fminf(fmaxf(factor, 0.2f), 10.0f);
            if (accept){ t += dtc; cur ^= 1; }
            dt = dtc * factor;
            if (t >= 1.0f - 1e-6f) done = 1;
        }
    }

    // ---- final copy ----
    for (int q=gt; q<NQ; q+=gstride)
        ((float4*)out)[q] = __ldcg((const float4*)g_yf[cur] + q);
}

// ============ launch ============
extern "C" void kernel_launch(void* const* d_in, const int* in_sizes, int n_in,
                              void* d_out, int out_size){
    const float* x = 0; const float* w[2] = {0,0}; const float* b[2] = {0,0};
    int nw=0, nb_=0;
    for (int i=0;i<n_in;i++){
        if (in_sizes[i] == NTOT) x = (const float*)d_in[i];
        else if (in_sizes[i] == WSIZE){ if (nw<2) w[nw++] = (const float*)d_in[i]; }
        else if (in_sizes[i] == CH){ if (nb_<2) b[nb_++] = (const float*)d_in[i]; }
    }
    cudaFuncSetAttribute(k_solver, cudaFuncAttributeMaxDynamicSharedMemorySize, CONV_SMEM);
    cudaFuncSetAttribute(k_solver, cudaFuncAttributePreferredSharedMemoryCarveout, 100);
    k_solver<<<GRID, NTHREADS, CONV_SMEM>>>(x, w[0], b[0], w[1], b[1], (float*)d_out);
}

// round 10
// speedup vs baseline: 1.3594x; 1.3594x over previous
#include <cuda_runtime.h>
#include <cuda_fp16.h>
#include <stdint.h>
#include <math.h>

#define CH 128
#define NPIX 32768              // 32*32*32
#define NTOT (NPIX*CH)          // 4194304
#define NQ (NTOT/4)
#define WSIZE (3*3*129*128)
#define NWB (9*128*128)         // 147456
#define MAX_STEPS 32
#define GRID 256
#define NTHREADS 256
#define NTILE 256

// ---- Dormand-Prince coefficients ----
#define C10 0.2f
#define C20 ((float)(3.0/40.0))
#define C21 ((float)(9.0/40.0))
#define C30 ((float)(44.0/45.0))
#define C31 ((float)(-56.0/15.0))
#define C32 ((float)(32.0/9.0))
#define C40 ((float)(19372.0/6561.0))
#define C41 ((float)(-25360.0/2187.0))
#define C42 ((float)(64448.0/6561.0))
#define C43 ((float)(-212.0/729.0))
#define C50 ((float)(9017.0/3168.0))
#define C51 ((float)(-355.0/33.0))
#define C52 ((float)(46732.0/5247.0))
#define C53 ((float)(49.0/176.0))
#define C54 ((float)(-5103.0/18656.0))
#define B0c ((float)(35.0/384.0))
#define B2c ((float)(500.0/1113.0))
#define B3c ((float)(125.0/192.0))
#define B4c ((float)(-2187.0/6784.0))
#define B5c ((float)(11.0/84.0))
#define E0c ((float)(35.0/384.0 - 5179.0/57600.0))
#define E2c ((float)(500.0/1113.0 - 7571.0/16695.0))
#define E3c ((float)(125.0/192.0 - 393.0/640.0))
#define E4c ((float)(-2187.0/6784.0 + 92097.0/339200.0))
#define E5c ((float)(11.0/84.0 - 187.0/2100.0))
#define E6c ((float)(-1.0/40.0))

// ---- Persistent state ----
__device__ __align__(16) float g_yf[2][NTOT];        // ping-pong fp32 y ([cur^1] holds y5)
__device__ __align__(16) float g_k[7][NTOT];
__device__ __align__(16) __half g_yh[2][NTOT];       // fp16 mirrors
__device__ __align__(16) __half g_tmph[NTOT];
__device__ __align__(16) __half g_hh[NTOT];
__device__ __align__(16) __half g_wh[2][NWB];        // [conv][tap*16384 + co*128 + ci]
__device__ float g_tw[2][9][128];
__device__ double g_part[NTILE];
__device__ unsigned g_arrive, g_gen;                 // grid barrier (zero-init)

// ---- conv smem layout ----
// A tile resident w/ halo: 6 rows x 34 px, each px = 128ci*2B = 256B, padded to 272B
#define A_ROWB 272
#define A_ENT  204               // 6*34
#define A_BYTES (A_ENT*A_ROWB)   // 55488
// W ring: 3 stages of 128 rows x (64ci = 128B + 16B pad = 144B)
#define W_ROWB 144
#define W_STG  (128*W_ROWB)      // 18432
#define W_RING A_BYTES
#define CONV_SMEM (A_BYTES + 3*W_STG)   // 110784

// ============ PTX wrappers (base ISA, valid for compute_103) ============
__device__ __forceinline__ uint32_t smem_u32(const void* p){
    uint32_t a;
    asm("{ .reg .u64 t; cvta.to.shared.u64 t, %1; cvt.u32.u64 %0, t; }" : "=r"(a) : "l"(p));
    return a;
}
__device__ __forceinline__ void cpa16(uint32_t dst, const void* src, uint32_t sz){
    asm volatile("cp.async.cg.shared.global [%0], [%1], 16, %2;" :: "r"(dst), "l"(src), "r"(sz));
}
#define CP_COMMIT() asm volatile("cp.async.commit_group;" ::: "memory")
#define CP_WAIT1()  asm volatile("cp.async.wait_group 1;" ::: "memory")
#define CP_WAIT0()  asm volatile("cp.async.wait_group 0;" ::: "memory")

__device__ __forceinline__ void ldm4(uint32_t* r, uint32_t addr){
    asm volatile("ldmatrix.sync.aligned.m8n8.x4.shared.b16 {%0,%1,%2,%3}, [%4];"
        : "=r"(r[0]), "=r"(r[1]), "=r"(r[2]), "=r"(r[3]) : "r"(addr));
}
__device__ __forceinline__ void mma16816(float* c, const uint32_t* a, uint32_t b0, uint32_t b1){
    asm volatile("mma.sync.aligned.m16n8k16.row.col.f32.f16.f16.f32 "
        "{%0,%1,%2,%3}, {%4,%5,%6,%7}, {%8,%9}, {%0,%1,%2,%3};"
        : "+f"(c[0]), "+f"(c[1]), "+f"(c[2]), "+f"(c[3])
        : "r"(a[0]), "r"(a[1]), "r"(a[2]), "r"(a[3]), "r"(b0), "r"(b1));
}
__device__ __forceinline__ uint32_t pk2h(__half a, __half b){
    return (uint32_t)__half_as_ushort(a) | ((uint32_t)__half_as_ushort(b) << 16);
}
__device__ __forceinline__ void h_store4(__half* Hp, int e, float4 v){
    uint2 H = make_uint2(pk2h(__float2half(v.x), __float2half(v.y)),
                         pk2h(__float2half(v.z), __float2half(v.w)));
    *(uint2*)(Hp + e) = H;
}

// ---- grid-wide sense barrier (all GRID CTAs resident) ----
__device__ __forceinline__ void gsync(){
    __threadfence();
    __syncthreads();
    if (threadIdx.x == 0){
        unsigned g;
        asm volatile("ld.acquire.gpu.u32 %0, [%1];" : "=r"(g) : "l"(&g_gen));
        unsigned old;
        asm volatile("atom.add.release.gpu.u32 %0, [%1], 1;" : "=r"(old) : "l"(&g_arrive) : "memory");
        if (old == GRID-1){
            asm volatile("st.relaxed.gpu.u32 [%0], 0;" :: "l"(&g_arrive) : "memory");
            asm volatile("st.release.gpu.u32 [%0], %1;" :: "l"(&g_gen), "r"(g+1) : "memory");
        } else {
            unsigned cur;
            do {
                __nanosleep(64);
                asm volatile("ld.acquire.gpu.u32 %0, [%1];" : "=r"(cur) : "l"(&g_gen));
            } while (cur == g);
        }
    }
    __syncthreads();
}

#define LDK(j) __ldcg((const float2*)(g_k[j]+idx))

// ============ conv phase: CTA tile 128pix x 128co; 8 warps, warp tile 32x64 ============
// A resident in smem with halo (loaded once); W streamed through 3-stage ring.
template<int WSEL>
__device__ __forceinline__ void conv_phase(
    uint32_t sb, int tile, int s,
    const float* __restrict__ Bias, float dtc, float tval, int cur,
    double* sdErr)
{
    const int tid  = threadIdx.x;
    const int wid  = tid >> 5;
    const int lane = tid & 31;

    const __half* __restrict__ X = (WSEL==0) ? ((s==0) ? g_yh[cur] : g_tmph) : g_hh;
    const __half* __restrict__ Wg = g_wh[WSEL];

    // ---- A tile load: 6 halo rows x 34 padded px x 128 ci ----
    const int n_img = tile >> 3;
    const int h0 = (tile & 7) << 2;          // first owned image row
    {
        const __half* Xi = X + ((long)n_img << 17);   // 32*32*128 per image
        #pragma unroll
        for (int j=0; j<13; ++j){
            int sl = tid + j*256;
            if (sl < 204*16){
                int e = sl >> 4, seg = sl & 15;
                int hr = e / 34, wc = e - hr*34;
                int gr = h0 + hr - 1, gw = wc - 1;
                bool v = ((unsigned)gr < 32u) && ((unsigned)gw < 32u);
                long off = v ? (((long)(gr*32 + gw)) << 7) + seg*8 : 0;
                cpa16(sb + (uint32_t)(e*A_ROWB + seg*16), Xi + off, v ? 16u : 0u);
            }
        }
        CP_COMMIT();
    }

    // ---- W loader geometry: 4 slots/thread -> (row 0..127, seg 0..7) ----
    auto load_w = [&](int c, int st){
        const int tap = c >> 1, ci0 = (c & 1) << 6;
        const uint32_t base = sb + W_RING + st*W_STG;
        const int wbase = tap*16384 + ci0;
        #pragma unroll
        for (int j=0;j<4;j++){
            int sl = tid + j*256;
            int row = sl >> 3, seg = sl & 7;
            cpa16(base + (uint32_t)(row*W_ROWB + seg*16), Wg + (wbase + row*128 + seg*8), 16u);
        }
    };

    // ---- compute geometry: warp (wid&3)->m0, (wid>>2)->n0 ----
    const int m0 = (wid & 3) * 32;
    const int n0 = (wid >> 2) * 64;
    // A ldmatrix per-lane base for each m-tile (owned pixel -> padded entry)
    uint32_t abase[2];
    #pragma unroll
    for (int mt=0; mt<2; ++mt){
        int px = m0 + (lane & 15) + mt*16;    // 0..127 owned pixel
        int lr = px >> 5, w = px & 31;
        abase[mt] = (uint32_t)(((lr+1)*34 + (w+1))*A_ROWB + (lane >> 4)*16);
    }
    const uint32_t boffbase = (uint32_t)((n0 + (lane & 7) + ((lane >> 4) << 3))*W_ROWB + ((lane >> 3) & 1)*16);

    float acc[2][8][4];
    #pragma unroll
    for (int i=0;i<2;i++)
        #pragma unroll
        for (int j=0;j<8;j++)
            #pragma unroll
            for (int q=0;q<4;q++) acc[i][j][q]=0.f;

    load_w(0,0); CP_COMMIT();
    load_w(1,1); CP_COMMIT();

    #pragma unroll 1
    for (int c=0; c<18; ++c){
        if (c==17) CP_WAIT0(); else CP_WAIT1();
        __syncthreads();
        if (c<16){ load_w(c+2, (c+2)%3); CP_COMMIT(); }

        const int tap = c >> 1, ci0 = (c & 1) << 6;
        const int dh = tap/3 - 1, dw = tap - (tap/3)*3 - 1;
        const uint32_t ashift = (uint32_t)((dh*34 + dw)*A_ROWB + ci0*2);
        const uint32_t aoff0 = sb + abase[0] + ashift;
        const uint32_t aoff1 = sb + abase[1] + ashift;
        const uint32_t boff = sb + W_RING + (c%3)*W_STG + boffbase;
        #pragma unroll
        for (int k16=0; k16<4; ++k16){
            const uint32_t kb = (uint32_t)(k16*32);
            uint32_t a0[4], a1[4];
            ldm4(a0, aoff0 + kb);
            ldm4(a1, aoff1 + kb);
            #pragma unroll
            for (int nt=0;nt<4;nt++){
                uint32_t b[4];
                ldm4(b, boff + (uint32_t)(nt*16*W_ROWB) + kb);
                mma16816(acc[0][2*nt],   a0, b[0], b[1]);
                mma16816(acc[0][2*nt+1], a0, b[2], b[3]);
                mma16816(acc[1][2*nt],   a1, b[0], b[1]);
                mma16816(acc[1][2*nt+1], a1, b[2], b[3]);
            }
        }
    }

    // ---- epilogue: + t-channel + bias, relu, store (+ fused combine / y5 / err) ----
    const int gID = lane >> 2, tq = lane & 3;
    const int mglob = tile*128;
    double errsum = 0.0;
    #pragma unroll
    for (int mt=0; mt<2; ++mt){
        #pragma unroll
        for (int rr=0; rr<2; ++rr){
            int r = m0 + mt*16 + rr*8 + gID;
            int m = mglob + r;
            int hp = (m >> 5) & 31, wp = m & 31;
            int cat = ((hp==0)?0:(hp==31)?6:3) + ((wp==0)?0:(wp==31)?2:1);
            const float* tw = g_tw[WSEL][cat];
            #pragma unroll
            for (int nf=0; nf<8; ++nf){
                int col = n0 + nf*8 + tq*2;
                float v0 = fmaxf(acc[mt][nf][rr*2+0] + tval*tw[col]   + Bias[col],   0.f);
                float v1 = fmaxf(acc[mt][nf][rr*2+1] + tval*tw[col+1] + Bias[col+1], 0.f);
                int idx = m*128 + col;
                if (WSEL==0){
                    *(uint32_t*)(g_hh + idx) = pk2h(__float2half(v0), __float2half(v1));
                } else {
                    *(float2*)(g_k[s] + idx) = make_float2(v0, v1);
                    if (s <= 5){
                        float2 y = __ldcg((const float2*)(g_yf[cur] + idx));
                        float c0, c1;
                        if (s==0){ c0 = C10*v0; c1 = C10*v1; }
                        else if (s==1){
                            float2 k0=LDK(0);
                            c0 = C20*k0.x + C21*v0; c1 = C20*k0.y + C21*v1;
                        } else if (s==2){
                            float2 k0=LDK(0), k1=LDK(1);
                            c0 = C30*k0.x + C31*k1.x + C32*v0;
                            c1 = C30*k0.y + C31*k1.y + C32*v1;
                        } else if (s==3){
                            float2 k0=LDK(0), k1=LDK(1), k2=LDK(2);
                            c0 = C40*k0.x + C41*k1.x + C42*k2.x + C43*v0;
                            c1 = C40*k0.y + C41*k1.y + C42*k2.y + C43*v1;
                        } else if (s==4){
                            float2 k0=LDK(0), k1=LDK(1), k2=LDK(2), k3=LDK(3);
                            c0 = C50*k0.x + C51*k1.x + C52*k2.x + C53*k3.x + C54*v0;
                            c1 = C50*k0.y + C51*k1.y + C52*k2.y + C53*k3.y + C54*v1;
                        } else {
                            float2 k0=LDK(0), k2=LDK(2), k3=LDK(3), k4=LDK(4);
                            c0 = B0c*k0.x + B2c*k2.x + B3c*k3.x + B4c*k4.x + B5c*v0;
                            c1 = B0c*k0.y + B2c*k2.y + B3c*k3.y + B4c*k4.y + B5c*v1;
                        }
                        float t0 = y.x + dtc*c0, t1 = y.y + dtc*c1;
                        uint32_t pk = pk2h(__float2half(t0), __float2half(t1));
                        *(uint32_t*)(g_tmph + idx) = pk;
                        if (s==5){
                            *(float2*)(g_yf[cur^1] + idx) = make_float2(t0, t1);
                            *(uint32_t*)(g_yh[cur^1] + idx) = pk;
                        }
                    } else {
                        float2 k0=LDK(0), k2=LDK(2), k3=LDK(3), k4=LDK(4), k5=LDK(5);
                        float2 y  = __ldcg((const float2*)(g_yf[cur]   + idx));
                        float2 y5 = __ldcg((const float2*)(g_yf[cur^1] + idx));
                        float e0 = dtc*(E0c*k0.x + E2c*k2.x + E3c*k3.x + E4c*k4.x + E5c*k5.x + E6c*v0);
                        float e1 = dtc*(E0c*k0.y + E2c*k2.y + E3c*k3.y + E4c*k4.y + E5c*k5.y + E6c*v1);
                        float sc0 = 1e-3f + 1e-3f*fmaxf(fabsf(y.x), fabsf(y5.x));
                        float sc1 = 1e-3f + 1e-3f*fmaxf(fabsf(y.y), fabsf(y5.y));
                        float r0 = e0/sc0, r1 = e1/sc1;
                        errsum += (double)r0*(double)r0 + (double)r1*(double)r1;
                    }
                }
            }
        }
    }
    if (WSEL==1 && s==6){
        sdErr[tid] = errsum;
        __syncthreads();
        for (int o=128; o>0; o>>=1){
            if (tid < o) sdErr[tid] += sdErr[tid+o];
            __syncthreads();
        }
        if (tid==0) g_part[tile] = sdErr[0];
    }
}

// ============ the single persistent kernel ============
__global__ __launch_bounds__(NTHREADS,2)
void k_solver(const float* __restrict__ x,
              const float* __restrict__ w1, const float* __restrict__ b1,
              const float* __restrict__ w2, const float* __restrict__ b2,
              float* __restrict__ out)
{
    extern __shared__ __align__(16) char dsm[];
    __shared__ double sd[NTHREADS];
    const uint32_t sb = smem_u32(dsm);
    const int bid = blockIdx.x, tid = threadIdx.x;
    const int gt = bid*NTHREADS + tid;
    const int gstride = GRID*NTHREADS;

    // ---- prep: weights (transposed fp16) ----
    for (int i=gt; i<2*NWB; i+=gstride){
        int conv = i / NWB, r = i % NWB;
        int tap = r >> 14, co = (r >> 7) & 127, ci = r & 127;
        float v = (conv ? w2 : w1)[(tap*129 + ci)*128 + co];
        g_wh[conv][r] = __float2half(v);
    }
    // ---- prep: t-channel weight sums per border category ----
    if (bid==0){
        int conv = tid >> 7, co = tid & 127;
        const float* w = conv ? w2 : w1;
        for (int cat=0; cat<9; cat++){
            int hc = cat/3, wc = cat%3;
            float ssum = 0.f;
            for (int tap=0; tap<9; tap++){
                int dh = tap/3 - 1, dw = tap%3 - 1;
                bool okh = !((hc==0 && dh<0) || (hc==2 && dh>0));
                bool okw = !((wc==0 && dw<0) || (wc==2 && dw>0));
                if (okh && okw) ssum += w[(tap*129 + 128)*128 + co];
            }
            g_tw[conv][cat][co] = ssum;
        }
    }
    // ---- init y ----
    for (int q=gt; q<NQ; q+=gstride){
        float4 v = ((const float4*)x)[q];
        ((float4*)g_yf[0])[q] = v;
        h_store4(g_yh[0], q*4, v);
    }
    gsync();

    // ---- per-CTA solver state (identical in every CTA) ----
    float t = 0.f, dt = 0.05f;
    int cur = 0, done = 0;
    const float TC[7] = {0.f, 0.2f, 0.3f, 0.8f, (float)(8.0/9.0), 1.f, 1.f};

    for (int it=0; it<MAX_STEPS; ++it){
        if (done) break;
        const float dtc = fminf(dt, 1.0f - t);
        for (int s=0; s<7; ++s){
            const float tval = t + TC[s]*dtc;
            conv_phase<0>(sb, bid, s, b1, dtc, tval, cur, sd);   // h
            gsync();
            conv_phase<1>(sb, bid, s, b2, dtc, tval, cur, sd);   // k_s (+fused)
            gsync();
        }
        // ---- controller, computed redundantly & identically in every CTA ----
        {
            double v=0.0;
            for (int i=tid; i<NTILE; i+=NTHREADS) v += __ldcg(&g_part[i]);
            sd[tid]=v; __syncthreads();
            for (int o=128; o>0; o>>=1){ if (tid<o) sd[tid]+=sd[tid+o]; __syncthreads(); }
            float err_norm = sqrtf((float)(sd[0] / (double)NTOT));
            __syncthreads();
            err_norm = fmaxf(err_norm, 1e-10f);
            int accept = (err_norm <= 1.0f) ? 1 : 0;
            float factor = 0.9f * powf(err_norm, -0.2f);
            factor = fminf(fmaxf(factor, 0.2f), 10.0f);
            if (accept){ t += dtc; cur ^= 1; }
            dt = dtc * factor;
            if (t >= 1.0f - 1e-6f) done = 1;
        }
    }

    // ---- final copy ----
    for (int q=gt; q<NQ; q+=gstride)
        ((float4*)out)[q] = __ldcg((const float4*)g_yf[cur] + q);
}

// ============ launch ============
extern "C" void kernel_launch(void* const* d_in, const int* in_sizes, int n_in,
                              void* d_out, int out_size){
    const float* x = 0; const float* w[2] = {0,0}; const float* b[2] = {0,0};
    int nw=0, nb_=0;
    for (int i=0;i<n_in;i++){
        if (in_sizes[i] == NTOT) x = (const float*)d_in[i];
        else if (in_sizes[i] == WSIZE){ if (nw<2) w[nw++] = (const float*)d_in[i]; }
        else if (in_sizes[i] == CH){ if (nb_<2) b[nb_++] = (const float*)d_in[i]; }
    }
    cudaFuncSetAttribute(k_solver, cudaFuncAttributeMaxDynamicSharedMemorySize, CONV_SMEM);
    cudaFuncSetAttribute(k_solver, cudaFuncAttributePreferredSharedMemoryCarveout, 100);
    k_solver<<<GRID, NTHREADS, CONV_SMEM>>>(x, w[0], b[0], w[1], b[1], (float*)d_out);
}

// round 11
// speedup vs baseline: 1.4452x; 1.0631x over previous
#include <cuda_runtime.h>
#include <cuda_fp16.h>
#include <stdint.h>
#include <math.h>

#define CH 128
#define NPIX 32768              // 32*32*32
#define NTOT (NPIX*CH)          // 4194304
#define NQ (NTOT/4)
#define WSIZE (3*3*129*128)
#define NWB (9*128*128)         // 147456
#define MAX_STEPS 32
#define GRID 256
#define NTHREADS 256
#define NTILE 256

// ---- Dormand-Prince coefficients ----
#define C10 0.2f
#define C20 ((float)(3.0/40.0))
#define C21 ((float)(9.0/40.0))
#define C30 ((float)(44.0/45.0))
#define C31 ((float)(-56.0/15.0))
#define C32 ((float)(32.0/9.0))
#define C40 ((float)(19372.0/6561.0))
#define C41 ((float)(-25360.0/2187.0))
#define C42 ((float)(64448.0/6561.0))
#define C43 ((float)(-212.0/729.0))
#define C50 ((float)(9017.0/3168.0))
#define C51 ((float)(-355.0/33.0))
#define C52 ((float)(46732.0/5247.0))
#define C53 ((float)(49.0/176.0))
#define C54 ((float)(-5103.0/18656.0))
#define B0c ((float)(35.0/384.0))
#define B2c ((float)(500.0/1113.0))
#define B3c ((float)(125.0/192.0))
#define B4c ((float)(-2187.0/6784.0))
#define B5c ((float)(11.0/84.0))
#define E0c ((float)(35.0/384.0 - 5179.0/57600.0))
#define E2c ((float)(500.0/1113.0 - 7571.0/16695.0))
#define E3c ((float)(125.0/192.0 - 393.0/640.0))
#define E4c ((float)(-2187.0/6784.0 + 92097.0/339200.0))
#define E5c ((float)(11.0/84.0 - 187.0/2100.0))
#define E6c ((float)(-1.0/40.0))

// ---- Persistent state ----
__device__ __align__(16) float g_yf[2][NTOT];        // ping-pong fp32 y ([cur^1] holds y5)
__device__ __align__(16) float g_k[7][NTOT];
__device__ __align__(16) __half g_yh[2][NTOT];       // fp16 mirrors
__device__ __align__(16) __half g_tmph[NTOT];
__device__ __align__(16) __half g_hh[NTOT];
__device__ __align__(16) __half g_wh[2][NWB];        // [conv][tap*16384 + co*128 + ci]
__device__ float g_tw[2][9][128];
__device__ double g_part[NTILE];
__device__ unsigned g_arrive, g_gen;                 // grid barrier (zero-init)

// ---- conv smem layout ----
// A tile resident w/ halo: 6 rows x 34 px, each px = 128ci*2B = 256B, padded to 272B
#define A_ROWB 272
#define A_ENT  204               // 6*34
#define A_BYTES (A_ENT*A_ROWB)   // 55488
// W ring: 3 stages of 128 rows x (64ci = 128B + 16B pad = 144B)
#define W_ROWB 144
#define W_STG  (128*W_ROWB)      // 18432
#define W_RING A_BYTES
#define CONV_SMEM (A_BYTES + 3*W_STG)   // 110784
// epilogue staging buffer: reuses W stages 0-1 region (sb+W_RING .. +34816)
#define STG_ROWB 272             // 64 floats + 16B pad

// ============ PTX wrappers (base ISA, valid for compute_103) ============
__device__ __forceinline__ uint32_t smem_u32(const void* p){
    uint32_t a;
    asm("{ .reg .u64 t; cvta.to.shared.u64 t, %1; cvt.u32.u64 %0, t; }" : "=r"(a) : "l"(p));
    return a;
}
__device__ __forceinline__ void cpa16(uint32_t dst, const void* src, uint32_t sz){
    asm volatile("cp.async.cg.shared.global [%0], [%1], 16, %2;" :: "r"(dst), "l"(src), "r"(sz));
}
#define CP_COMMIT() asm volatile("cp.async.commit_group;" ::: "memory")
#define CP_WAIT1()  asm volatile("cp.async.wait_group 1;" ::: "memory")
#define CP_WAIT0()  asm volatile("cp.async.wait_group 0;" ::: "memory")

__device__ __forceinline__ void ldm4(uint32_t* r, uint32_t addr){
    asm volatile("ldmatrix.sync.aligned.m8n8.x4.shared.b16 {%0,%1,%2,%3}, [%4];"
        : "=r"(r[0]), "=r"(r[1]), "=r"(r[2]), "=r"(r[3]) : "r"(addr));
}
__device__ __forceinline__ void mma16816(float* c, const uint32_t* a, uint32_t b0, uint32_t b1){
    asm volatile("mma.sync.aligned.m16n8k16.row.col.f32.f16.f16.f32 "
        "{%0,%1,%2,%3}, {%4,%5,%6,%7}, {%8,%9}, {%0,%1,%2,%3};"
        : "+f"(c[0]), "+f"(c[1]), "+f"(c[2]), "+f"(c[3])
        : "r"(a[0]), "r"(a[1]), "r"(a[2]), "r"(a[3]), "r"(b0), "r"(b1));
}
__device__ __forceinline__ uint32_t pk2h(__half a, __half b){
    return (uint32_t)__half_as_ushort(a) | ((uint32_t)__half_as_ushort(b) << 16);
}
__device__ __forceinline__ void h_store4(__half* Hp, int e, float4 v){
    uint2 H = make_uint2(pk2h(__float2half(v.x), __float2half(v.y)),
                         pk2h(__float2half(v.z), __float2half(v.w)));
    *(uint2*)(Hp + e) = H;
}

// ---- grid-wide sense barrier (all GRID CTAs resident) ----
__device__ __forceinline__ void gsync(){
    __threadfence();
    __syncthreads();
    if (threadIdx.x == 0){
        unsigned g;
        asm volatile("ld.acquire.gpu.u32 %0, [%1];" : "=r"(g) : "l"(&g_gen));
        unsigned old;
        asm volatile("atom.add.release.gpu.u32 %0, [%1], 1;" : "=r"(old) : "l"(&g_arrive) : "memory");
        if (old == GRID-1){
            asm volatile("st.relaxed.gpu.u32 [%0], 0;" :: "l"(&g_arrive) : "memory");
            asm volatile("st.release.gpu.u32 [%0], %1;" :: "l"(&g_gen), "r"(g+1) : "memory");
        } else {
            unsigned cur;
            do {
                __nanosleep(64);
                asm volatile("ld.acquire.gpu.u32 %0, [%1];" : "=r"(cur) : "l"(&g_gen));
            } while (cur == g);
        }
    }
    __syncthreads();
}

#define LDK4(j) __ldcg((const float4*)(g_k[j]+idx))

// ============ conv phase: CTA tile 128pix x 128co; 8 warps, warp tile 32x64 ============
// A resident in smem with halo (loaded once); W streamed through 3-stage ring.
// Epilogue staged through smem for fully-coalesced global I/O.
template<int WSEL>
__device__ __forceinline__ void conv_phase(
    char* dsm, uint32_t sb, int tile, int s,
    const float* __restrict__ Bias, float dtc, float tval, int cur,
    double* sdErr)
{
    const int tid  = threadIdx.x;
    const int wid  = tid >> 5;
    const int lane = tid & 31;

    const __half* __restrict__ X = (WSEL==0) ? ((s==0) ? g_yh[cur] : g_tmph) : g_hh;
    const __half* __restrict__ Wg = g_wh[WSEL];

    // ---- A tile load: 6 halo rows x 34 padded px x 128 ci ----
    const int n_img = tile >> 3;
    const int h0 = (tile & 7) << 2;          // first owned image row
    {
        const __half* Xi = X + ((long)n_img << 17);   // 32*32*128 per image
        #pragma unroll
        for (int j=0; j<13; ++j){
            int sl = tid + j*256;
            if (sl < 204*16){
                int e = sl >> 4, seg = sl & 15;
                int hr = e / 34, wc = e - hr*34;
                int gr = h0 + hr - 1, gw = wc - 1;
                bool v = ((unsigned)gr < 32u) && ((unsigned)gw < 32u);
                long off = v ? (((long)(gr*32 + gw)) << 7) + seg*8 : 0;
                cpa16(sb + (uint32_t)(e*A_ROWB + seg*16), Xi + off, v ? 16u : 0u);
            }
        }
        CP_COMMIT();
    }

    // ---- W loader: 4 slots/thread -> (row 0..127, seg 0..7) ----
    auto load_w = [&](int c, int st){
        const int tap = c >> 1, ci0 = (c & 1) << 6;
        const uint32_t base = sb + W_RING + st*W_STG;
        const int wbase = tap*16384 + ci0;
        #pragma unroll
        for (int j=0;j<4;j++){
            int sl = tid + j*256;
            int row = sl >> 3, seg = sl & 7;
            cpa16(base + (uint32_t)(row*W_ROWB + seg*16), Wg + (wbase + row*128 + seg*8), 16u);
        }
    };

    // ---- compute geometry: warp (wid&3)->m0, (wid>>2)->n0 ----
    const int m0 = (wid & 3) * 32;
    const int n0 = (wid >> 2) * 64;
    uint32_t abase[2];
    #pragma unroll
    for (int mt=0; mt<2; ++mt){
        int px = m0 + (lane & 15) + mt*16;    // 0..127 owned pixel
        int lr = px >> 5, w = px & 31;
        abase[mt] = (uint32_t)(((lr+1)*34 + (w+1))*A_ROWB + (lane >> 4)*16);
    }
    const uint32_t boffbase = (uint32_t)((n0 + (lane & 7) + ((lane >> 4) << 3))*W_ROWB + ((lane >> 3) & 1)*16);

    float acc[2][8][4];
    #pragma unroll
    for (int i=0;i<2;i++)
        #pragma unroll
        for (int j=0;j<8;j++)
            #pragma unroll
            for (int q=0;q<4;q++) acc[i][j][q]=0.f;

    load_w(0,0); CP_COMMIT();
    load_w(1,1); CP_COMMIT();

    #pragma unroll 1
    for (int c=0; c<18; ++c){
        if (c==17) CP_WAIT0(); else CP_WAIT1();
        __syncthreads();
        if (c<16){ load_w(c+2, (c+2)%3); CP_COMMIT(); }

        const int tap = c >> 1, ci0 = (c & 1) << 6;
        const int dh = tap/3 - 1, dw = tap - (tap/3)*3 - 1;
        const uint32_t ashift = (uint32_t)((dh*34 + dw)*A_ROWB + ci0*2);
        const uint32_t aoff0 = sb + abase[0] + ashift;
        const uint32_t aoff1 = sb + abase[1] + ashift;
        const uint32_t boff = sb + W_RING + (c%3)*W_STG + boffbase;
        #pragma unroll
        for (int k16=0; k16<4; ++k16){
            const uint32_t kb = (uint32_t)(k16*32);
            uint32_t a0[4], a1[4];
            ldm4(a0, aoff0 + kb);
            ldm4(a1, aoff1 + kb);
            #pragma unroll
            for (int nt=0;nt<4;nt++){
                uint32_t b[4];
                ldm4(b, boff + (uint32_t)(nt*16*W_ROWB) + kb);
                mma16816(acc[0][2*nt],   a0, b[0], b[1]);
                mma16816(acc[0][2*nt+1], a0, b[2], b[3]);
                mma16816(acc[1][2*nt],   a1, b[0], b[1]);
                mma16816(acc[1][2*nt+1], a1, b[2], b[3]);
            }
        }
    }

    // ---- epilogue: stage fragments through smem, then coalesced global I/O ----
    const int mglob = tile*128;
    char* stg = dsm + W_RING;     // 128 rows x 272B = 34816B (disjoint from W stage 2)
    double errsum = 0.0;
    const int gID = lane >> 2, tq = lane & 3;

    #pragma unroll 1
    for (int nh=0; nh<2; ++nh){
        __syncthreads();
        if ((wid >> 2) == nh){
            #pragma unroll
            for (int mt=0; mt<2; ++mt)
                #pragma unroll
                for (int rr=0; rr<2; ++rr){
                    int row = m0 + mt*16 + rr*8 + gID;
                    #pragma unroll
                    for (int nf=0; nf<8; ++nf)
                        *(float2*)(stg + row*STG_ROWB + (nf*8 + tq*2)*4) =
                            make_float2(acc[mt][nf][rr*2], acc[mt][nf][rr*2+1]);
                }
        }
        __syncthreads();
        // slot pass: 256 threads x 8 slots; slot -> (row, float4-seg); fully coalesced
        #pragma unroll 1
        for (int j=0; j<8; ++j){
            int sl = tid + j*256;
            int row = sl >> 4, seg = sl & 15;
            float4 a = *(const float4*)(stg + row*STG_ROWB + seg*16);
            int col = nh*64 + seg*4;
            int m = mglob + row;
            int hp = (m >> 5) & 31, wp = m & 31;
            int cat = ((hp==0)?0:(hp==31)?6:3) + ((wp==0)?0:(wp==31)?2:1);
            float4 tw4 = *(const float4*)(g_tw[WSEL][cat] + col);
            float4 b4  = *(const float4*)(Bias + col);
            float4 v;
            v.x = fmaxf(a.x + tval*tw4.x + b4.x, 0.f);
            v.y = fmaxf(a.y + tval*tw4.y + b4.y, 0.f);
            v.z = fmaxf(a.z + tval*tw4.z + b4.z, 0.f);
            v.w = fmaxf(a.w + tval*tw4.w + b4.w, 0.f);
            int idx = m*128 + col;
            if (WSEL==0){
                *(uint2*)(g_hh + idx) = make_uint2(pk2h(__float2half(v.x), __float2half(v.y)),
                                                   pk2h(__float2half(v.z), __float2half(v.w)));
            } else {
                *(float4*)(g_k[s] + idx) = v;
                if (s <= 5){
                    float4 y = __ldcg((const float4*)(g_yf[cur] + idx));
                    float4 c4;
                    if (s==0){
                        c4.x = C10*v.x; c4.y = C10*v.y; c4.z = C10*v.z; c4.w = C10*v.w;
                    } else if (s==1){
                        float4 k0=LDK4(0);
                        c4.x = C20*k0.x + C21*v.x; c4.y = C20*k0.y + C21*v.y;
                        c4.z = C20*k0.z + C21*v.z; c4.w = C20*k0.w + C21*v.w;
                    } else if (s==2){
                        float4 k0=LDK4(0), k1=LDK4(1);
                        c4.x = C30*k0.x + C31*k1.x + C32*v.x;
                        c4.y = C30*k0.y + C31*k1.y + C32*v.y;
                        c4.z = C30*k0.z + C31*k1.z + C32*v.z;
                        c4.w = C30*k0.w + C31*k1.w + C32*v.w;
                    } else if (s==3){
                        float4 k0=LDK4(0), k1=LDK4(1), k2=LDK4(2);
                        c4.x = C40*k0.x + C41*k1.x + C42*k2.x + C43*v.x;
                        c4.y = C40*k0.y + C41*k1.y + C42*k2.y + C43*v.y;
                        c4.z = C40*k0.z + C41*k1.z + C42*k2.z + C43*v.z;
                        c4.w = C40*k0.w + C41*k1.w + C42*k2.w + C43*v.w;
                    } else if (s==4){
                        float4 k0=LDK4(0), k1=LDK4(1), k2=LDK4(2), k3=LDK4(3);
                        c4.x = C50*k0.x + C51*k1.x + C52*k2.x + C53*k3.x + C54*v.x;
                        c4.y = C50*k0.y + C51*k1.y + C52*k2.y + C53*k3.y + C54*v.y;
                        c4.z = C50*k0.z + C51*k1.z + C52*k2.z + C53*k3.z + C54*v.z;
                        c4.w = C50*k0.w + C51*k1.w + C52*k2.w + C53*k3.w + C54*v.w;
                    } else {
                        float4 k0=LDK4(0), k2=LDK4(2), k3=LDK4(3), k4=LDK4(4);
                        c4.x = B0c*k0.x + B2c*k2.x + B3c*k3.x + B4c*k4.x + B5c*v.x;
                        c4.y = B0c*k0.y + B2c*k2.y + B3c*k3.y + B4c*k4.y + B5c*v.y;
                        c4.z = B0c*k0.z + B2c*k2.z + B3c*k3.z + B4c*k4.z + B5c*v.z;
                        c4.w = B0c*k0.w + B2c*k2.w + B3c*k3.w + B4c*k4.w + B5c*v.w;
                    }
                    float4 tv;
                    tv.x = y.x + dtc*c4.x; tv.y = y.y + dtc*c4.y;
                    tv.z = y.z + dtc*c4.z; tv.w = y.w + dtc*c4.w;
                    uint2 pk = make_uint2(pk2h(__float2half(tv.x), __float2half(tv.y)),
                                          pk2h(__float2half(tv.z), __float2half(tv.w)));
                    *(uint2*)(g_tmph + idx) = pk;
                    if (s==5){
                        *(float4*)(g_yf[cur^1] + idx) = tv;
                        *(uint2*)(g_yh[cur^1] + idx) = pk;
                    }
                } else {
                    float4 k0=LDK4(0), k2=LDK4(2), k3=LDK4(3), k4=LDK4(4), k5=LDK4(5);
                    float4 y  = __ldcg((const float4*)(g_yf[cur]   + idx));
                    float4 y5 = __ldcg((const float4*)(g_yf[cur^1] + idx));
                    float e0 = dtc*(E0c*k0.x + E2c*k2.x + E3c*k3.x + E4c*k4.x + E5c*k5.x + E6c*v.x);
                    float e1 = dtc*(E0c*k0.y + E2c*k2.y + E3c*k3.y + E4c*k4.y + E5c*k5.y + E6c*v.y);
                    float e2 = dtc*(E0c*k0.z + E2c*k2.z + E3c*k3.z + E4c*k4.z + E5c*k5.z + E6c*v.z);
                    float e3 = dtc*(E0c*k0.w + E2c*k2.w + E3c*k3.w + E4c*k4.w + E5c*k5.w + E6c*v.w);
                    float sc0 = 1e-3f + 1e-3f*fmaxf(fabsf(y.x), fabsf(y5.x));
                    float sc1 = 1e-3f + 1e-3f*fmaxf(fabsf(y.y), fabsf(y5.y));
                    float sc2 = 1e-3f + 1e-3f*fmaxf(fabsf(y.z), fabsf(y5.z));
                    float sc3 = 1e-3f + 1e-3f*fmaxf(fabsf(y.w), fabsf(y5.w));
                    float r0 = e0/sc0, r1 = e1/sc1, r2 = e2/sc2, r3 = e3/sc3;
                    errsum += (double)r0*(double)r0 + (double)r1*(double)r1
                            + (double)r2*(double)r2 + (double)r3*(double)r3;
                }
            }
        }
    }
    if (WSEL==1 && s==6){
        sdErr[tid] = errsum;
        __syncthreads();
        for (int o=128; o>0; o>>=1){
            if (tid < o) sdErr[tid] += sdErr[tid+o];
            __syncthreads();
        }
        if (tid==0) g_part[tile] = sdErr[0];
    }
}

// ============ the single persistent kernel ============
__global__ __launch_bounds__(NTHREADS,2)
void k_solver(const float* __restrict__ x,
              const float* __restrict__ w1, const float* __restrict__ b1,
              const float* __restrict__ w2, const float* __restrict__ b2,
              float* __restrict__ out)
{
    extern __shared__ __align__(16) char dsm[];
    __shared__ double sd[NTHREADS];
    const uint32_t sb = smem_u32(dsm);
    const int bid = blockIdx.x, tid = threadIdx.x;
    const int gt = bid*NTHREADS + tid;
    const int gstride = GRID*NTHREADS;

    // ---- prep: weights (transposed fp16) ----
    for (int i=gt; i<2*NWB; i+=gstride){
        int conv = i / NWB, r = i % NWB;
        int tap = r >> 14, co = (r >> 7) & 127, ci = r & 127;
        float v = (conv ? w2 : w1)[(tap*129 + ci)*128 + co];
        g_wh[conv][r] = __float2half(v);
    }
    // ---- prep: t-channel weight sums per border category ----
    if (bid==0){
        int conv = tid >> 7, co = tid & 127;
        const float* w = conv ? w2 : w1;
        for (int cat=0; cat<9; cat++){
            int hc = cat/3, wc = cat%3;
            float ssum = 0.f;
            for (int tap=0; tap<9; tap++){
                int dh = tap/3 - 1, dw = tap%3 - 1;
                bool okh = !((hc==0 && dh<0) || (hc==2 && dh>0));
                bool okw = !((wc==0 && dw<0) || (wc==2 && dw>0));
                if (okh && okw) ssum += w[(tap*129 + 128)*128 + co];
            }
            g_tw[conv][cat][co] = ssum;
        }
    }
    // ---- init y ----
    for (int q=gt; q<NQ; q+=gstride){
        float4 v = ((const float4*)x)[q];
        ((float4*)g_yf[0])[q] = v;
        h_store4(g_yh[0], q*4, v);
    }
    gsync();

    // ---- per-CTA solver state (identical in every CTA) ----
    float t = 0.f, dt = 0.05f;
    int cur = 0, done = 0;
    const float TC[7] = {0.f, 0.2f, 0.3f, 0.8f, (float)(8.0/9.0), 1.f, 1.f};

    for (int it=0; it<MAX_STEPS; ++it){
        if (done) break;
        const float dtc = fminf(dt, 1.0f - t);
        for (int s=0; s<7; ++s){
            const float tval = t + TC[s]*dtc;
            conv_phase<0>(dsm, sb, bid, s, b1, dtc, tval, cur, sd);   // h
            gsync();
            conv_phase<1>(dsm, sb, bid, s, b2, dtc, tval, cur, sd);   // k_s (+fused)
            gsync();
        }
        // ---- controller, computed redundantly & identically in every CTA ----
        {
            double v=0.0;
            for (int i=tid; i<NTILE; i+=NTHREADS) v += __ldcg(&g_part[i]);
            sd[tid]=v; __syncthreads();
            for (int o=128; o>0; o>>=1){ if (tid<o) sd[tid]+=sd[tid+o]; __syncthreads(); }
            float err_norm = sqrtf((float)(sd[0] / (double)NTOT));
            __syncthreads();
            err_norm = fmaxf(err_norm, 1e-10f);
            int accept = (err_norm <= 1.0f) ? 1 : 0;
            float factor = 0.9f * powf(err_norm, -0.2f);
            factor = fminf(fmaxf(factor, 0.2f), 10.0f);
            if (accept){ t += dtc; cur ^= 1; }
            dt = dtc * factor;
            if (t >= 1.0f - 1e-6f) done = 1;
        }
    }

    // ---- final copy ----
    for (int q=gt; q<NQ; q+=gstride)
        ((float4*)out)[q] = __ldcg((const float4*)g_yf[cur] + q);
}

// ============ launch ============
extern "C" void kernel_launch(void* const* d_in, const int* in_sizes, int n_in,
                              void* d_out, int out_size){
    const float* x = 0; const float* w[2] = {0,0}; const float* b[2] = {0,0};
    int nw=0, nb_=0;
    for (int i=0;i<n_in;i++){
        if (in_sizes[i] == NTOT) x = (const float*)d_in[i];
        else if (in_sizes[i] == WSIZE){ if (nw<2) w[nw++] = (const float*)d_in[i]; }
        else if (in_sizes[i] == CH){ if (nb_<2) b[nb_++] = (const float*)d_in[i]; }
    }
    cudaFuncSetAttribute(k_solver, cudaFuncAttributeMaxDynamicSharedMemorySize, CONV_SMEM);
    cudaFuncSetAttribute(k_solver, cudaFuncAttributePreferredSharedMemoryCarveout, 100);
    k_solver<<<GRID, NTHREADS, CONV_SMEM>>>(x, w[0], b[0], w[1], b[1], (float*)d_out);
}

// round 12
// speedup vs baseline: 1.6454x; 1.1385x over previous
#include <cuda_runtime.h>
#include <cuda_fp16.h>
#include <stdint.h>
#include <math.h>

#define CH 128
#define NPIX 32768              // 32*32*32
#define NTOT (NPIX*CH)          // 4194304
#define NQ (NTOT/4)
#define WSIZE (3*3*129*128)
#define NWB (9*128*128)         // 147456
#define MAX_STEPS 32
#define GRID 128
#define NTHREADS 512
#define NTILE 128               // tiles of 256 pixels

// ---- Dormand-Prince coefficients ----
#define C10 0.2f
#define C20 ((float)(3.0/40.0))
#define C21 ((float)(9.0/40.0))
#define C30 ((float)(44.0/45.0))
#define C31 ((float)(-56.0/15.0))
#define C32 ((float)(32.0/9.0))
#define C40 ((float)(19372.0/6561.0))
#define C41 ((float)(-25360.0/2187.0))
#define C42 ((float)(64448.0/6561.0))
#define C43 ((float)(-212.0/729.0))
#define C50 ((float)(9017.0/3168.0))
#define C51 ((float)(-355.0/33.0))
#define C52 ((float)(46732.0/5247.0))
#define C53 ((float)(49.0/176.0))
#define C54 ((float)(-5103.0/18656.0))
#define B0c ((float)(35.0/384.0))
#define B2c ((float)(500.0/1113.0))
#define B3c ((float)(125.0/192.0))
#define B4c ((float)(-2187.0/6784.0))
#define B5c ((float)(11.0/84.0))
#define E0c ((float)(35.0/384.0 - 5179.0/57600.0))
#define E2c ((float)(500.0/1113.0 - 7571.0/16695.0))
#define E3c ((float)(125.0/192.0 - 393.0/640.0))
#define E4c ((float)(-2187.0/6784.0 + 92097.0/339200.0))
#define E5c ((float)(11.0/84.0 - 187.0/2100.0))
#define E6c ((float)(-1.0/40.0))

// ---- Persistent state ----
__device__ __align__(16) float g_yf[2][NTOT];        // ping-pong fp32 y ([cur^1] holds y5)
__device__ __align__(16) float g_k[7][NTOT];
__device__ __align__(16) __half g_yh[2][NTOT];       // fp16 mirrors
__device__ __align__(16) __half g_tmph[NTOT];
__device__ __align__(16) __half g_hh[NTOT];
__device__ __align__(16) __half g_wh[2][NWB];        // [conv][tap*16384 + co*128 + ci]
__device__ float g_tw[2][9][128];
__device__ double g_part[NTILE];
__device__ unsigned g_arrive, g_gen;                 // grid barrier (zero-init)

// ---- conv smem layout ----
// A tile resident w/ halo: 10 rows x 34 px, each px = 128ci*2B = 256B, padded to 272B
#define A_ROWB 272
#define A_ENT  340               // 10*34
#define A_BYTES (A_ENT*A_ROWB)   // 92480
// W ring: 3 stages of 128 co-rows x (128ci = 256B + 16B pad = 272B)
#define W_ROWB 272
#define W_STG  (128*W_ROWB)      // 34816
#define W_RING A_BYTES
#define CONV_SMEM (A_BYTES + 3*W_STG)   // 196928
// epilogue staging: 256 rows x 272B at W_RING (all W consumed by then)
#define STG_ROWB 272

// ============ PTX wrappers (base ISA, valid for compute_103) ============
__device__ __forceinline__ uint32_t smem_u32(const void* p){
    uint32_t a;
    asm("{ .reg .u64 t; cvta.to.shared.u64 t, %1; cvt.u32.u64 %0, t; }" : "=r"(a) : "l"(p));
    return a;
}
__device__ __forceinline__ void cpa16(uint32_t dst, const void* src, uint32_t sz){
    asm volatile("cp.async.cg.shared.global [%0], [%1], 16, %2;" :: "r"(dst), "l"(src), "r"(sz));
}
#define CP_COMMIT() asm volatile("cp.async.commit_group;" ::: "memory")
#define CP_WAIT1()  asm volatile("cp.async.wait_group 1;" ::: "memory")
#define CP_WAIT0()  asm volatile("cp.async.wait_group 0;" ::: "memory")

__device__ __forceinline__ void ldm4(uint32_t* r, uint32_t addr){
    asm volatile("ldmatrix.sync.aligned.m8n8.x4.shared.b16 {%0,%1,%2,%3}, [%4];"
        : "=r"(r[0]), "=r"(r[1]), "=r"(r[2]), "=r"(r[3]) : "r"(addr));
}
__device__ __forceinline__ void mma16816(float* c, const uint32_t* a, uint32_t b0, uint32_t b1){
    asm volatile("mma.sync.aligned.m16n8k16.row.col.f32.f16.f16.f32 "
        "{%0,%1,%2,%3}, {%4,%5,%6,%7}, {%8,%9}, {%0,%1,%2,%3};"
        : "+f"(c[0]), "+f"(c[1]), "+f"(c[2]), "+f"(c[3])
        : "r"(a[0]), "r"(a[1]), "r"(a[2]), "r"(a[3]), "r"(b0), "r"(b1));
}
__device__ __forceinline__ uint32_t pk2h(__half a, __half b){
    return (uint32_t)__half_as_ushort(a) | ((uint32_t)__half_as_ushort(b) << 16);
}
__device__ __forceinline__ void h_store4(__half* Hp, int e, float4 v){
    uint2 H = make_uint2(pk2h(__float2half(v.x), __float2half(v.y)),
                         pk2h(__float2half(v.z), __float2half(v.w)));
    *(uint2*)(Hp + e) = H;
}

// ---- grid-wide sense barrier (all GRID CTAs resident) ----
__device__ __forceinline__ void gsync(){
    __threadfence();
    __syncthreads();
    if (threadIdx.x == 0){
        unsigned g;
        asm volatile("ld.acquire.gpu.u32 %0, [%1];" : "=r"(g) : "l"(&g_gen));
        unsigned old;
        asm volatile("atom.add.release.gpu.u32 %0, [%1], 1;" : "=r"(old) : "l"(&g_arrive) : "memory");
        if (old == GRID-1){
            asm volatile("st.relaxed.gpu.u32 [%0], 0;" :: "l"(&g_arrive) : "memory");
            asm volatile("st.release.gpu.u32 [%0], %1;" :: "l"(&g_gen), "r"(g+1) : "memory");
        } else {
            unsigned cur;
            do {
                __nanosleep(64);
                asm volatile("ld.acquire.gpu.u32 %0, [%1];" : "=r"(cur) : "l"(&g_gen));
            } while (cur == g);
        }
    }
    __syncthreads();
}

#define LDK4(j) __ldcg((const float4*)(g_k[j]+idx))

// ============ conv phase: CTA tile 256pix x 128co; 16 warps, warp tile 32x64 ============
// A resident in smem with halo (loaded once); W streamed as 9 full-128ci chunks, 3-stage ring.
template<int WSEL>
__device__ __forceinline__ void conv_phase(
    char* dsm, uint32_t sb, int tile, int s,
    const float* __restrict__ Bias, float dtc, float tval, int cur,
    double* sdErr)
{
    const int tid  = threadIdx.x;
    const int wid  = tid >> 5;
    const int lane = tid & 31;

    const __half* __restrict__ X = (WSEL==0) ? ((s==0) ? g_yh[cur] : g_tmph) : g_hh;
    const __half* __restrict__ Wg = g_wh[WSEL];

    // ---- A tile load: 10 halo rows x 34 padded px x 128 ci ----
    const int n_img = tile >> 2;
    const int h0 = (tile & 3) << 3;          // first owned image row (8 rows per tile)
    {
        const __half* Xi = X + ((long)n_img << 17);   // 32*32*128 per image
        #pragma unroll
        for (int j=0; j<11; ++j){
            int sl = tid + j*NTHREADS;
            if (sl < A_ENT*16){
                int e = sl >> 4, seg = sl & 15;
                int hr = e / 34, wc = e - hr*34;
                int gr = h0 + hr - 1, gw = wc - 1;
                bool v = ((unsigned)gr < 32u) && ((unsigned)gw < 32u);
                long off = v ? (((long)(gr*32 + gw)) << 7) + seg*8 : 0;
                cpa16(sb + (uint32_t)(e*A_ROWB + seg*16), Xi + off, v ? 16u : 0u);
            }
        }
        CP_COMMIT();
    }

    // ---- W loader: chunk = one tap, full 128 ci; 4 slots/thread ----
    auto load_w = [&](int tap, int st){
        const uint32_t base = sb + W_RING + st*W_STG;
        const int wbase = tap*16384;
        #pragma unroll
        for (int j=0;j<4;j++){
            int sl = tid + j*NTHREADS;
            int row = sl >> 4, seg = sl & 15;
            cpa16(base + (uint32_t)(row*W_ROWB + seg*16), Wg + (wbase + row*128 + seg*8), 16u);
        }
    };

    // ---- compute geometry: warp (wid&7)->m0, (wid>>3)->n0 ----
    const int m0 = (wid & 7) * 32;
    const int n0 = (wid >> 3) * 64;
    uint32_t abase[2];
    #pragma unroll
    for (int mt=0; mt<2; ++mt){
        int px = m0 + (lane & 15) + mt*16;    // 0..255 owned pixel
        int lr = px >> 5, w = px & 31;
        abase[mt] = (uint32_t)(((lr+1)*34 + (w+1))*A_ROWB + (lane >> 4)*16);
    }
    const uint32_t boffbase = (uint32_t)((n0 + (lane & 7) + ((lane >> 4) << 3))*W_ROWB + ((lane >> 3) & 1)*16);

    float acc[2][8][4];
    #pragma unroll
    for (int i=0;i<2;i++)
        #pragma unroll
        for (int j=0;j<8;j++)
            #pragma unroll
            for (int q=0;q<4;q++) acc[i][j][q]=0.f;

    load_w(0,0); CP_COMMIT();
    load_w(1,1); CP_COMMIT();

    #pragma unroll 1
    for (int c=0; c<9; ++c){
        if (c==8) CP_WAIT0(); else CP_WAIT1();
        __syncthreads();
        if (c<7){ load_w(c+2, (c+2)%3); CP_COMMIT(); }

        const int dh = c/3 - 1, dw = c - (c/3)*3 - 1;
        const uint32_t ashift = (uint32_t)((dh*34 + dw)*A_ROWB);
        const uint32_t aoff0 = sb + abase[0] + ashift;
        const uint32_t aoff1 = sb + abase[1] + ashift;
        const uint32_t boff = sb + W_RING + (c%3)*W_STG + boffbase;
        #pragma unroll
        for (int k16=0; k16<8; ++k16){
            const uint32_t kb = (uint32_t)(k16*32);
            uint32_t a0[4], a1[4];
            ldm4(a0, aoff0 + kb);
            ldm4(a1, aoff1 + kb);
            #pragma unroll
            for (int nt=0;nt<4;nt++){
                uint32_t b[4];
                ldm4(b, boff + (uint32_t)(nt*16*W_ROWB) + kb);
                mma16816(acc[0][2*nt],   a0, b[0], b[1]);
                mma16816(acc[0][2*nt+1], a0, b[2], b[3]);
                mma16816(acc[1][2*nt],   a1, b[0], b[1]);
                mma16816(acc[1][2*nt+1], a1, b[2], b[3]);
            }
        }
    }

    // ---- epilogue: stage fragments through smem, then coalesced global I/O ----
    const int mglob = tile*256;
    char* stg = dsm + W_RING;     // 256 rows x 272B = 69632B (W fully consumed)
    double errsum = 0.0;
    const int gID = lane >> 2, tq = lane & 3;

    #pragma unroll 1
    for (int nh=0; nh<2; ++nh){
        __syncthreads();
        if ((wid >> 3) == nh){
            #pragma unroll
            for (int mt=0; mt<2; ++mt)
                #pragma unroll
                for (int rr=0; rr<2; ++rr){
                    int row = m0 + mt*16 + rr*8 + gID;
                    #pragma unroll
                    for (int nf=0; nf<8; ++nf)
                        *(float2*)(stg + row*STG_ROWB + (nf*8 + tq*2)*4) =
                            make_float2(acc[mt][nf][rr*2], acc[mt][nf][rr*2+1]);
                }
        }
        __syncthreads();
        // slot pass: 512 threads x 8 slots; slot -> (row 0..255, float4-seg 0..15); coalesced
        #pragma unroll 1
        for (int j=0; j<8; ++j){
            int sl = tid + j*NTHREADS;
            int row = sl >> 4, seg = sl & 15;
            float4 a = *(const float4*)(stg + row*STG_ROWB + seg*16);
            int col = nh*64 + seg*4;
            int m = mglob + row;
            int hp = (m >> 5) & 31, wp = m & 31;
            int cat = ((hp==0)?0:(hp==31)?6:3) + ((wp==0)?0:(wp==31)?2:1);
            float4 tw4 = *(const float4*)(g_tw[WSEL][cat] + col);
            float4 b4  = *(const float4*)(Bias + col);
            float4 v;
            v.x = fmaxf(a.x + tval*tw4.x + b4.x, 0.f);
            v.y = fmaxf(a.y + tval*tw4.y + b4.y, 0.f);
            v.z = fmaxf(a.z + tval*tw4.z + b4.z, 0.f);
            v.w = fmaxf(a.w + tval*tw4.w + b4.w, 0.f);
            int idx = m*128 + col;
            if (WSEL==0){
                *(uint2*)(g_hh + idx) = make_uint2(pk2h(__float2half(v.x), __float2half(v.y)),
                                                   pk2h(__float2half(v.z), __float2half(v.w)));
            } else {
                *(float4*)(g_k[s] + idx) = v;
                if (s <= 5){
                    float4 y = __ldcg((const float4*)(g_yf[cur] + idx));
                    float4 c4;
                    if (s==0){
                        c4.x = C10*v.x; c4.y = C10*v.y; c4.z = C10*v.z; c4.w = C10*v.w;
                    } else if (s==1){
                        float4 k0=LDK4(0);
                        c4.x = C20*k0.x + C21*v.x; c4.y = C20*k0.y + C21*v.y;
                        c4.z = C20*k0.z + C21*v.z; c4.w = C20*k0.w + C21*v.w;
                    } else if (s==2){
                        float4 k0=LDK4(0), k1=LDK4(1);
                        c4.x = C30*k0.x + C31*k1.x + C32*v.x;
                        c4.y = C30*k0.y + C31*k1.y + C32*v.y;
                        c4.z = C30*k0.z + C31*k1.z + C32*v.z;
                        c4.w = C30*k0.w + C31*k1.w + C32*v.w;
                    } else if (s==3){
                        float4 k0=LDK4(0), k1=LDK4(1), k2=LDK4(2);
                        c4.x = C40*k0.x + C41*k1.x + C42*k2.x + C43*v.x;
                        c4.y = C40*k0.y + C41*k1.y + C42*k2.y + C43*v.y;
                        c4.z = C40*k0.z + C41*k1.z + C42*k2.z + C43*v.z;
                        c4.w = C40*k0.w + C41*k1.w + C42*k2.w + C43*v.w;
                    } else if (s==4){
                        float4 k0=LDK4(0), k1=LDK4(1), k2=LDK4(2), k3=LDK4(3);
                        c4.x = C50*k0.x + C51*k1.x + C52*k2.x + C53*k3.x + C54*v.x;
                        c4.y = C50*k0.y + C51*k1.y + C52*k2.y + C53*k3.y + C54*v.y;
                        c4.z = C50*k0.z + C51*k1.z + C52*k2.z + C53*k3.z + C54*v.z;
                        c4.w = C50*k0.w + C51*k1.w + C52*k2.w + C53*k3.w + C54*v.w;
                    } else {
                        float4 k0=LDK4(0), k2=LDK4(2), k3=LDK4(3), k4=LDK4(4);
                        c4.x = B0c*k0.x + B2c*k2.x + B3c*k3.x + B4c*k4.x + B5c*v.x;
                        c4.y = B0c*k0.y + B2c*k2.y + B3c*k3.y + B4c*k4.y + B5c*v.y;
                        c4.z = B0c*k0.z + B2c*k2.z + B3c*k3.z + B4c*k4.z + B5c*v.z;
                        c4.w = B0c*k0.w + B2c*k2.w + B3c*k3.w + B4c*k4.w + B5c*v.w;
                    }
                    float4 tv;
                    tv.x = y.x + dtc*c4.x; tv.y = y.y + dtc*c4.y;
                    tv.z = y.z + dtc*c4.z; tv.w = y.w + dtc*c4.w;
                    uint2 pk = make_uint2(pk2h(__float2half(tv.x), __float2half(tv.y)),
                                          pk2h(__float2half(tv.z), __float2half(tv.w)));
                    *(uint2*)(g_tmph + idx) = pk;
                    if (s==5){
                        *(float4*)(g_yf[cur^1] + idx) = tv;
                        *(uint2*)(g_yh[cur^1] + idx) = pk;
                    }
                } else {
                    float4 k0=LDK4(0), k2=LDK4(2), k3=LDK4(3), k4=LDK4(4), k5=LDK4(5);
                    float4 y  = __ldcg((const float4*)(g_yf[cur]   + idx));
                    float4 y5 = __ldcg((const float4*)(g_yf[cur^1] + idx));
                    float e0 = dtc*(E0c*k0.x + E2c*k2.x + E3c*k3.x + E4c*k4.x + E5c*k5.x + E6c*v.x);
                    float e1 = dtc*(E0c*k0.y + E2c*k2.y + E3c*k3.y + E4c*k4.y + E5c*k5.y + E6c*v.y);
                    float e2 = dtc*(E0c*k0.z + E2c*k2.z + E3c*k3.z + E4c*k4.z + E5c*k5.z + E6c*v.z);
                    float e3 = dtc*(E0c*k0.w + E2c*k2.w + E3c*k3.w + E4c*k4.w + E5c*k5.w + E6c*v.w);
                    float sc0 = 1e-3f + 1e-3f*fmaxf(fabsf(y.x), fabsf(y5.x));
                    float sc1 = 1e-3f + 1e-3f*fmaxf(fabsf(y.y), fabsf(y5.y));
                    float sc2 = 1e-3f + 1e-3f*fmaxf(fabsf(y.z), fabsf(y5.z));
                    float sc3 = 1e-3f + 1e-3f*fmaxf(fabsf(y.w), fabsf(y5.w));
                    float r0 = e0/sc0, r1 = e1/sc1, r2 = e2/sc2, r3 = e3/sc3;
                    errsum += (double)r0*(double)r0 + (double)r1*(double)r1
                            + (double)r2*(double)r2 + (double)r3*(double)r3;
                }
            }
        }
    }
    if (WSEL==1 && s==6){
        sdErr[tid] = errsum;
        __syncthreads();
        for (int o=256; o>0; o>>=1){
            if (tid < o) sdErr[tid] += sdErr[tid+o];
            __syncthreads();
        }
        if (tid==0) g_part[tile] = sdErr[0];
    }
}

// ============ the single persistent kernel ============
__global__ __launch_bounds__(NTHREADS,1)
void k_solver(const float* __restrict__ x,
              const float* __restrict__ w1, const float* __restrict__ b1,
              const float* __restrict__ w2, const float* __restrict__ b2,
              float* __restrict__ out)
{
    extern __shared__ __align__(16) char dsm[];
    __shared__ double sd[NTHREADS];
    const uint32_t sb = smem_u32(dsm);
    const int bid = blockIdx.x, tid = threadIdx.x;
    const int gt = bid*NTHREADS + tid;
    const int gstride = GRID*NTHREADS;

    // ---- prep: weights (transposed fp16) ----
    for (int i=gt; i<2*NWB; i+=gstride){
        int conv = i / NWB, r = i % NWB;
        int tap = r >> 14, co = (r >> 7) & 127, ci = r & 127;
        float v = (conv ? w2 : w1)[(tap*129 + ci)*128 + co];
        g_wh[conv][r] = __float2half(v);
    }
    // ---- prep: t-channel weight sums per border category ----
    if (bid==0 && tid<256){
        int conv = tid >> 7, co = tid & 127;
        const float* w = conv ? w2 : w1;
        for (int cat=0; cat<9; cat++){
            int hc = cat/3, wc = cat%3;
            float ssum = 0.f;
            for (int tap=0; tap<9; tap++){
                int dh = tap/3 - 1, dw = tap%3 - 1;
                bool okh = !((hc==0 && dh<0) || (hc==2 && dh>0));
                bool okw = !((wc==0 && dw<0) || (wc==2 && dw>0));
                if (okh && okw) ssum += w[(tap*129 + 128)*128 + co];
            }
            g_tw[conv][cat][co] = ssum;
        }
    }
    // ---- init y ----
    for (int q=gt; q<NQ; q+=gstride){
        float4 v = ((const float4*)x)[q];
        ((float4*)g_yf[0])[q] = v;
        h_store4(g_yh[0], q*4, v);
    }
    gsync();

    // ---- per-CTA solver state (identical in every CTA) ----
    float t = 0.f, dt = 0.05f;
    int cur = 0, done = 0;
    const float TC[7] = {0.f, 0.2f, 0.3f, 0.8f, (float)(8.0/9.0), 1.f, 1.f};

    for (int it=0; it<MAX_STEPS; ++it){
        if (done) break;
        const float dtc = fminf(dt, 1.0f - t);
        for (int s=0; s<7; ++s){
            const float tval = t + TC[s]*dtc;
            conv_phase<0>(dsm, sb, bid, s, b1, dtc, tval, cur, sd);   // h
            gsync();
            conv_phase<1>(dsm, sb, bid, s, b2, dtc, tval, cur, sd);   // k_s (+fused)
            gsync();
        }
        // ---- controller, computed redundantly & identically in every CTA ----
        {
            double v=0.0;
            for (int i=tid; i<NTILE; i+=NTHREADS) v += __ldcg(&g_part[i]);
            sd[tid]=v; __syncthreads();
            for (int o=256; o>0; o>>=1){ if (tid<o) sd[tid]+=sd[tid+o]; __syncthreads(); }
            float err_norm = sqrtf((float)(sd[0] / (double)NTOT));
            __syncthreads();
            err_norm = fmaxf(err_norm, 1e-10f);
            int accept = (err_norm <= 1.0f) ? 1 : 0;
            float factor = 0.9f * powf(err_norm, -0.2f);
            factor = fminf(fmaxf(factor, 0.2f), 10.0f);
            if (accept){ t += dtc; cur ^= 1; }
            dt = dtc * factor;
            if (t >= 1.0f - 1e-6f) done = 1;
        }
    }

    // ---- final copy ----
    for (int q=gt; q<NQ; q+=gstride)
        ((float4*)out)[q] = __ldcg((const float4*)g_yf[cur] + q);
}

// ============ launch ============
extern "C" void kernel_launch(void* const* d_in, const int* in_sizes, int n_in,
                              void* d_out, int out_size){
    const float* x = 0; const float* w[2] = {0,0}; const float* b[2] = {0,0};
    int nw=0, nb_=0;
    for (int i=0;i<n_in;i++){
        if (in_sizes[i] == NTOT) x = (const float*)d_in[i];
        else if (in_sizes[i] == WSIZE){ if (nw<2) w[nw++] = (const float*)d_in[i]; }
        else if (in_sizes[i] == CH){ if (nb_<2) b[nb_++] = (const float*)d_in[i]; }
    }
    cudaFuncSetAttribute(k_solver, cudaFuncAttributeMaxDynamicSharedMemorySize, CONV_SMEM);
    cudaFuncSetAttribute(k_solver, cudaFuncAttributePreferredSharedMemoryCarveout, 100);
    k_solver<<<GRID, NTHREADS, CONV_SMEM>>>(x, w[0], b[0], w[1], b[1], (float*)d_out);
}

// round 14
// speedup vs baseline: 1.6780x; 1.0198x over previous
#include <cuda_runtime.h>
#include <cuda_fp16.h>
#include <stdint.h>
#include <math.h>

#define CH 128
#define NPIX 32768              // 32*32*32
#define NTOT (NPIX*CH)          // 4194304
#define NQ (NTOT/4)
#define WSIZE (3*3*129*128)
#define NWB (9*128*128)         // 147456
#define MAX_STEPS 32
#define GRID 128
#define NTHREADS 512
#define NTILE 128               // tiles of 256 pixels

// ---- Dormand-Prince coefficients ----
#define C10 0.2f
#define C20 ((float)(3.0/40.0))
#define C21 ((float)(9.0/40.0))
#define C30 ((float)(44.0/45.0))
#define C31 ((float)(-56.0/15.0))
#define C32 ((float)(32.0/9.0))
#define C40 ((float)(19372.0/6561.0))
#define C41 ((float)(-25360.0/2187.0))
#define C42 ((float)(64448.0/6561.0))
#define C43 ((float)(-212.0/729.0))
#define C50 ((float)(9017.0/3168.0))
#define C51 ((float)(-355.0/33.0))
#define C52 ((float)(46732.0/5247.0))
#define C53 ((float)(49.0/176.0))
#define C54 ((float)(-5103.0/18656.0))
#define B0c ((float)(35.0/384.0))
#define B2c ((float)(500.0/1113.0))
#define B3c ((float)(125.0/192.0))
#define B4c ((float)(-2187.0/6784.0))
#define B5c ((float)(11.0/84.0))
#define E0c ((float)(35.0/384.0 - 5179.0/57600.0))
#define E2c ((float)(500.0/1113.0 - 7571.0/16695.0))
#define E3c ((float)(125.0/192.0 - 393.0/640.0))
#define E4c ((float)(-2187.0/6784.0 + 92097.0/339200.0))
#define E5c ((float)(11.0/84.0 - 187.0/2100.0))
#define E6c ((float)(-1.0/40.0))

// ---- Persistent state ----
__device__ __align__(16) float g_yf[2][NTOT];        // ping-pong fp32 y ([cur^1] holds y5)
__device__ __align__(16) float g_k[7][NTOT];
__device__ __align__(16) __half g_yh[2][NTOT];       // fp16 mirrors
__device__ __align__(16) __half g_tmph[NTOT];
__device__ __align__(16) __half g_hh[NTOT];
__device__ __align__(16) __half g_wh[2][NWB];        // [conv][tap*16384 + co*128 + ci]
__device__ float g_tw[2][9][128];
__device__ double g_part[NTILE];
__device__ unsigned g_arrive, g_gen;                 // grid barrier (zero-init)

// ---- conv smem layout ----
// A tile resident w/ halo: 10 rows x 34 px, each px = 128ci*2B = 256B, padded to 272B
#define A_ROWB 272
#define A_ENT  340               // 10*34
#define A_BYTES (A_ENT*A_ROWB)   // 92480
// W ring: 3 stages of 128 co-rows x (128ci = 256B + 16B pad = 272B)
#define W_ROWB 272
#define W_STG  (128*W_ROWB)      // 34816
#define W_RING A_BYTES
#define CONV_SMEM (A_BYTES + 3*W_STG)   // 196928
// epilogue staging: 256 rows x 272B at W_RING (all W consumed by then)
#define STG_ROWB 272

// ============ PTX wrappers (base ISA, valid for compute_103) ============
__device__ __forceinline__ uint32_t smem_u32(const void* p){
    uint32_t a;
    asm("{ .reg .u64 t; cvta.to.shared.u64 t, %1; cvt.u32.u64 %0, t; }" : "=r"(a) : "l"(p));
    return a;
}
__device__ __forceinline__ void cpa16(uint32_t dst, const void* src, uint32_t sz){
    asm volatile("cp.async.cg.shared.global [%0], [%1], 16, %2;" :: "r"(dst), "l"(src), "r"(sz));
}
#define CP_COMMIT() asm volatile("cp.async.commit_group;" ::: "memory")
#define CP_WAIT1()  asm volatile("cp.async.wait_group 1;" ::: "memory")
#define CP_WAIT0()  asm volatile("cp.async.wait_group 0;" ::: "memory")

__device__ __forceinline__ void ldm4(uint32_t* r, uint32_t addr){
    asm volatile("ldmatrix.sync.aligned.m8n8.x4.shared.b16 {%0,%1,%2,%3}, [%4];"
        : "=r"(r[0]), "=r"(r[1]), "=r"(r[2]), "=r"(r[3]) : "r"(addr));
}
__device__ __forceinline__ void mma16816(float* c, const uint32_t* a, uint32_t b0, uint32_t b1){
    asm volatile("mma.sync.aligned.m16n8k16.row.col.f32.f16.f16.f32 "
        "{%0,%1,%2,%3}, {%4,%5,%6,%7}, {%8,%9}, {%0,%1,%2,%3};"
        : "+f"(c[0]), "+f"(c[1]), "+f"(c[2]), "+f"(c[3])
        : "r"(a[0]), "r"(a[1]), "r"(a[2]), "r"(a[3]), "r"(b0), "r"(b1));
}
__device__ __forceinline__ uint32_t pk2h(__half a, __half b){
    return (uint32_t)__half_as_ushort(a) | ((uint32_t)__half_as_ushort(b) << 16);
}
__device__ __forceinline__ void h_store4(__half* Hp, int e, float4 v){
    uint2 H = make_uint2(pk2h(__float2half(v.x), __float2half(v.y)),
                         pk2h(__float2half(v.z), __float2half(v.w)));
    *(uint2*)(Hp + e) = H;
}

// ---- grid-wide sense barrier (all GRID CTAs resident) ----
__device__ __forceinline__ void gsync(){
    __threadfence();
    __syncthreads();
    if (threadIdx.x == 0){
        unsigned g;
        asm volatile("ld.acquire.gpu.u32 %0, [%1];" : "=r"(g) : "l"(&g_gen));
        unsigned old;
        asm volatile("atom.add.release.gpu.u32 %0, [%1], 1;" : "=r"(old) : "l"(&g_arrive) : "memory");
        if (old == GRID-1){
            asm volatile("st.relaxed.gpu.u32 [%0], 0;" :: "l"(&g_arrive) : "memory");
            asm volatile("st.release.gpu.u32 [%0], %1;" :: "l"(&g_gen), "r"(g+1) : "memory");
        } else {
            unsigned cur;
            do {
                __nanosleep(64);
                asm volatile("ld.acquire.gpu.u32 %0, [%1];" : "=r"(cur) : "l"(&g_gen));
            } while (cur == g);
        }
    }
    __syncthreads();
}

#define LDK4(j) __ldcg((const float4*)(g_k[j]+idx))

// ---- prefetch W chunks 0,1 for the NEXT phase (weights immutable; legal across gsync) ----
__device__ __forceinline__ void prefetch_w01(uint32_t sb, const __half* __restrict__ Wg, int tid){
    #pragma unroll
    for (int st=0; st<2; ++st){
        const uint32_t base = sb + W_RING + st*W_STG;
        const int wbase = st*16384;
        #pragma unroll
        for (int j=0;j<4;j++){
            int sl = tid + j*NTHREADS;
            int row = sl >> 4, seg = sl & 15;
            cpa16(base + (uint32_t)(row*W_ROWB + seg*16), Wg + (wbase + row*128 + seg*8), 16u);
        }
        CP_COMMIT();
    }
}

// ============ conv phase: CTA tile 256pix x 128co; 16 warps, warp tile 32x64 ============
// A resident in smem; owned 256 px written by previous phase's epilogue (fullA=0) or
// loaded fully from global (fullA=1). Halo (84 entries) always loaded post-gsync.
// W chunks 0,1 prefetched by the caller before the preceding gsync.
template<int WSEL>
__device__ __forceinline__ void conv_phase(
    char* dsm, uint32_t sb, int tile, int s,
    const float* __restrict__ Bias, float dtc, float tval, int cur,
    double* sdErr, int fullA)
{
    const int tid  = threadIdx.x;
    const int wid  = tid >> 5;
    const int lane = tid & 31;

    const __half* __restrict__ X = (WSEL==0) ? ((s==0) ? g_yh[cur] : g_tmph) : g_hh;
    const __half* __restrict__ Wg = g_wh[WSEL];

    const int n_img = tile >> 2;
    const int h0 = (tile & 3) << 3;          // first owned image row (8 rows per tile)
    const __half* Xi = X + ((long)n_img << 17);   // 32*32*128 per image

    if (fullA){
        // full A tile: 10 halo rows x 34 padded px x 128 ci
        #pragma unroll
        for (int j=0; j<11; ++j){
            int sl = tid + j*NTHREADS;
            if (sl < A_ENT*16){
                int e = sl >> 4, seg = sl & 15;
                int hr = e / 34, wc = e - hr*34;
                int gr = h0 + hr - 1, gw = wc - 1;
                bool v = ((unsigned)gr < 32u) && ((unsigned)gw < 32u);
                long off = v ? (((long)(gr*32 + gw)) << 7) + seg*8 : 0;
                cpa16(sb + (uint32_t)(e*A_ROWB + seg*16), Xi + off, v ? 16u : 0u);
            }
        }
    } else {
        // halo only: rows hr=0 and hr=9 (34 entries each) + side columns rows 1..8 (16)
        #pragma unroll
        for (int j=0; j<3; ++j){
            int sl = tid + j*NTHREADS;
            if (sl < 84*16){
                int ei = sl >> 4, seg = sl & 15;
                int hr, wc;
                if (ei < 34){ hr = 0; wc = ei; }
                else if (ei < 68){ hr = 9; wc = ei - 34; }
                else { int k = ei - 68; hr = 1 + (k >> 1); wc = (k & 1) ? 33 : 0; }
                int e = hr*34 + wc;
                int gr = h0 + hr - 1, gw = wc - 1;
                bool v = ((unsigned)gr < 32u) && ((unsigned)gw < 32u);
                long off = v ? (((long)(gr*32 + gw)) << 7) + seg*8 : 0;
                cpa16(sb + (uint32_t)(e*A_ROWB + seg*16), Xi + off, v ? 16u : 0u);
            }
        }
    }
    CP_COMMIT();

    // ---- W loader: chunk = one tap, full 128 ci; 4 slots/thread ----
    auto load_w = [&](int tap, int st){
        const uint32_t base = sb + W_RING + st*W_STG;
        const int wbase = tap*16384;
        #pragma unroll
        for (int j=0;j<4;j++){
            int sl = tid + j*NTHREADS;
            int row = sl >> 4, seg = sl & 15;
            cpa16(base + (uint32_t)(row*W_ROWB + seg*16), Wg + (wbase + row*128 + seg*8), 16u);
        }
    };

    // ---- compute geometry: warp (wid&7)->m0, (wid>>3)->n0 ----
    const int m0 = (wid & 7) * 32;
    const int n0 = (wid >> 3) * 64;
    uint32_t abase[2];
    #pragma unroll
    for (int mt=0; mt<2; ++mt){
        int px = m0 + (lane & 15) + mt*16;    // 0..255 owned pixel
        int lr = px >> 5, w = px & 31;
        abase[mt] = (uint32_t)(((lr+1)*34 + (w+1))*A_ROWB + (lane >> 4)*16);
    }
    const uint32_t boffbase = (uint32_t)((n0 + (lane & 7) + ((lane >> 4) << 3))*W_ROWB + ((lane >> 3) & 1)*16);

    float acc[2][8][4];
    #pragma unroll
    for (int i=0;i<2;i++)
        #pragma unroll
        for (int j=0;j<8;j++)
            #pragma unroll
            for (int q=0;q<4;q++) acc[i][j][q]=0.f;

    // groups outstanding at entry: W0, W1 (prefetched pre-gsync), A/halo (just committed)
    #pragma unroll 1
    for (int c=0; c<9; ++c){
        if (c==0 || c==8) CP_WAIT0(); else CP_WAIT1();
        __syncthreads();
        if (c<7){ load_w(c+2, (c+2)%3); CP_COMMIT(); }

        const int dh = c/3 - 1, dw = c - (c/3)*3 - 1;
        const uint32_t ashift = (uint32_t)((dh*34 + dw)*A_ROWB);
        const uint32_t aoff0 = sb + abase[0] + ashift;
        const uint32_t aoff1 = sb + abase[1] + ashift;
        const uint32_t boff = sb + W_RING + (c%3)*W_STG + boffbase;
        #pragma unroll
        for (int k16=0; k16<8; ++k16){
            const uint32_t kb = (uint32_t)(k16*32);
            uint32_t a0[4], a1[4];
            ldm4(a0, aoff0 + kb);
            ldm4(a1, aoff1 + kb);
            #pragma unroll
            for (int nt=0;nt<4;nt++){
                uint32_t b[4];
                ldm4(b, boff + (uint32_t)(nt*16*W_ROWB) + kb);
                mma16816(acc[0][2*nt],   a0, b[0], b[1]);
                mma16816(acc[0][2*nt+1], a0, b[2], b[3]);
                mma16816(acc[1][2*nt],   a1, b[0], b[1]);
                mma16816(acc[1][2*nt+1], a1, b[2], b[3]);
            }
        }
    }

    // ---- epilogue: stage fragments through smem, then coalesced global I/O ----
    // Also writes fp16 results into the A buffer's owned entries for the NEXT phase.
    const int mglob = tile*256;
    char* stg = dsm + W_RING;     // 256 rows x 272B = 69632B (W fully consumed)
    double errsum = 0.0;

    #pragma unroll 1
    for (int nh=0; nh<2; ++nh){
        __syncthreads();
        if ((wid >> 3) == nh){
            const int gID = lane >> 2, tq = lane & 3;
            #pragma unroll
            for (int mt=0; mt<2; ++mt)
                #pragma unroll
                for (int rr=0; rr<2; ++rr){
                    int row = m0 + mt*16 + rr*8 + gID;
                    #pragma unroll
                    for (int nf=0; nf<8; ++nf)
                        *(float2*)(stg + row*STG_ROWB + (nf*8 + tq*2)*4) =
                            make_float2(acc[mt][nf][rr*2], acc[mt][nf][rr*2+1]);
                }
        }
        __syncthreads();
        // slot pass: 512 threads x 8 slots; slot -> (row 0..255, float4-seg 0..15); coalesced
        #pragma unroll 1
        for (int j=0; j<8; ++j){
            int sl = tid + j*NTHREADS;
            int row = sl >> 4, seg = sl & 15;
            float4 a = *(const float4*)(stg + row*STG_ROWB + seg*16);
            int col = nh*64 + seg*4;
            int m = mglob + row;
            int hp = (m >> 5) & 31, wp = m & 31;
            int cat = ((hp==0)?0:(hp==31)?6:3) + ((wp==0)?0:(wp==31)?2:1);
            float4 tw4 = *(const float4*)(g_tw[WSEL][cat] + col);
            float4 b4  = *(const float4*)(Bias + col);
            float4 v;
            v.x = fmaxf(a.x + tval*tw4.x + b4.x, 0.f);
            v.y = fmaxf(a.y + tval*tw4.y + b4.y, 0.f);
            v.z = fmaxf(a.z + tval*tw4.z + b4.z, 0.f);
            v.w = fmaxf(a.w + tval*tw4.w + b4.w, 0.f);
            int idx = m*128 + col;
            // A-buffer owned entry for this row/col (fp16, for next phase's reuse)
            const int lr = row >> 5, w = row & 31;
            const uint32_t ae = (uint32_t)(((lr+1)*34 + (w+1))*A_ROWB) + (uint32_t)(col*2);
            if (WSEL==0){
                uint2 pk = make_uint2(pk2h(__float2half(v.x), __float2half(v.y)),
                                      pk2h(__float2half(v.z), __float2half(v.w)));
                *(uint2*)(g_hh + idx) = pk;
                *(uint2*)(dsm + ae) = pk;        // h -> conv2's A
            } else {
                *(float4*)(g_k[s] + idx) = v;
                if (s <= 5){
                    float4 y = __ldcg((const float4*)(g_yf[cur] + idx));
                    float4 c4;
                    if (s==0){
                        c4.x = C10*v.x; c4.y = C10*v.y; c4.z = C10*v.z; c4.w = C10*v.w;
                    } else if (s==1){
                        float4 k0=LDK4(0);
                        c4.x = C20*k0.x + C21*v.x; c4.y = C20*k0.y + C21*v.y;
                        c4.z = C20*k0.z + C21*v.z; c4.w = C20*k0.w + C21*v.w;
                    } else if (s==2){
                        float4 k0=LDK4(0), k1=LDK4(1);
                        c4.x = C30*k0.x + C31*k1.x + C32*v.x;
                        c4.y = C30*k0.y + C31*k1.y + C32*v.y;
                        c4.z = C30*k0.z + C31*k1.z + C32*v.z;
                        c4.w = C30*k0.w + C31*k1.w + C32*v.w;
                    } else if (s==3){
                        float4 k0=LDK4(0), k1=LDK4(1), k2=LDK4(2);
                        c4.x = C40*k0.x + C41*k1.x + C42*k2.x + C43*v.x;
                        c4.y = C40*k0.y + C41*k1.y + C42*k2.y + C43*v.y;
                        c4.z = C40*k0.z + C41*k1.z + C42*k2.z + C43*v.z;
                        c4.w = C40*k0.w + C41*k1.w + C42*k2.w + C43*v.w;
                    } else if (s==4){
                        float4 k0=LDK4(0), k1=LDK4(1), k2=LDK4(2), k3=LDK4(3);
                        c4.x = C50*k0.x + C51*k1.x + C52*k2.x + C53*k3.x + C54*v.x;
                        c4.y = C50*k0.y + C51*k1.y + C52*k2.y + C53*k3.y + C54*v.y;
                        c4.z = C50*k0.z + C51*k1.z + C52*k2.z + C53*k3.z + C54*v.z;
                        c4.w = C50*k0.w + C51*k1.w + C52*k2.w + C53*k3.w + C54*v.w;
                    } else {
                        float4 k0=LDK4(0), k2=LDK4(2), k3=LDK4(3), k4=LDK4(4);
                        c4.x = B0c*k0.x + B2c*k2.x + B3c*k3.x + B4c*k4.x + B5c*v.x;
                        c4.y = B0c*k0.y + B2c*k2.y + B3c*k3.y + B4c*k4.y + B5c*v.y;
                        c4.z = B0c*k0.z + B2c*k2.z + B3c*k3.z + B4c*k4.z + B5c*v.z;
                        c4.w = B0c*k0.w + B2c*k2.w + B3c*k3.w + B4c*k4.w + B5c*v.w;
                    }
                    float4 tv;
                    tv.x = y.x + dtc*c4.x; tv.y = y.y + dtc*c4.y;
                    tv.z = y.z + dtc*c4.z; tv.w = y.w + dtc*c4.w;
                    uint2 pk = make_uint2(pk2h(__float2half(tv.x), __float2half(tv.y)),
                                          pk2h(__float2half(tv.z), __float2half(tv.w)));
                    *(uint2*)(g_tmph + idx) = pk;
                    *(uint2*)(dsm + ae) = pk;    // tmp -> next conv1's A
                    if (s==5){
                        *(float4*)(g_yf[cur^1] + idx) = tv;
                        *(uint2*)(g_yh[cur^1] + idx) = pk;
                    }
                } else {
                    float4 k0=LDK4(0), k2=LDK4(2), k3=LDK4(3), k4=LDK4(4), k5=LDK4(5);
                    float4 y  = __ldcg((const float4*)(g_yf[cur]   + idx));
                    float4 y5 = __ldcg((const float4*)(g_yf[cur^1] + idx));
                    float e0 = dtc*(E0c*k0.x + E2c*k2.x + E3c*k3.x + E4c*k4.x + E5c*k5.x + E6c*v.x);
                    float e1 = dtc*(E0c*k0.y + E2c*k2.y + E3c*k3.y + E4c*k4.y + E5c*k5.y + E6c*v.y);
                    float e2 = dtc*(E0c*k0.z + E2c*k2.z + E3c*k3.z + E4c*k4.z + E5c*k5.z + E6c*v.z);
                    float e3 = dtc*(E0c*k0.w + E2c*k2.w + E3c*k3.w + E4c*k4.w + E5c*k5.w + E6c*v.w);
                    float sc0 = 1e-3f + 1e-3f*fmaxf(fabsf(y.x), fabsf(y5.x));
                    float sc1 = 1e-3f + 1e-3f*fmaxf(fabsf(y.y), fabsf(y5.y));
                    float sc2 = 1e-3f + 1e-3f*fmaxf(fabsf(y.z), fabsf(y5.z));
                    float sc3 = 1e-3f + 1e-3f*fmaxf(fabsf(y.w), fabsf(y5.w));
                    float r0 = e0/sc0, r1 = e1/sc1, r2 = e2/sc2, r3 = e3/sc3;
                    errsum += (double)r0*(double)r0 + (double)r1*(double)r1
                            + (double)r2*(double)r2 + (double)r3*(double)r3;
                }
            }
        }
    }
    if (WSEL==1 && s==6){
        sdErr[tid] = errsum;
        __syncthreads();
        for (int o=256; o>0; o>>=1){
            if (tid < o) sdErr[tid] += sdErr[tid+o];
            __syncthreads();
        }
        if (tid==0) g_part[tile] = sdErr[0];
    }
}

// ============ the single persistent kernel ============
__global__ __launch_bounds__(NTHREADS,1)
void k_solver(const float* __restrict__ x,
              const float* __restrict__ w1, const float* __restrict__ b1,
              const float* __restrict__ w2, const float* __restrict__ b2,
              float* __restrict__ out)
{
    extern __shared__ __align__(16) char dsm[];
    __shared__ double sd[NTHREADS];
    const uint32_t sb = smem_u32(dsm);
    const int bid = blockIdx.x, tid = threadIdx.x;
    const int gt = bid*NTHREADS + tid;
    const int gstride = GRID*NTHREADS;

    // ---- prep: weights (transposed fp16) ----
    for (int i=gt; i<2*NWB; i+=gstride){
        int conv = i / NWB, r = i % NWB;
        int tap = r >> 14, co = (r >> 7) & 127, ci = r & 127;
        float v = (conv ? w2 : w1)[(tap*129 + ci)*128 + co];
        g_wh[conv][r] = __float2half(v);
    }
    // ---- prep: t-channel weight sums per border category ----
    if (bid==0 && tid<256){
        int conv = tid >> 7, co = tid & 127;
        const float* w = conv ? w2 : w1;
        for (int cat=0; cat<9; cat++){
            int hc = cat/3, wc = cat%3;
            float ssum = 0.f;
            for (int tap=0; tap<9; tap++){
                int dh = tap/3 - 1, dw = tap%3 - 1;
                bool okh = !((hc==0 && dh<0) || (hc==2 && dh>0));
                bool okw = !((wc==0 && dw<0) || (wc==2 && dw>0));
                if (okh && okw) ssum += w[(tap*129 + 128)*128 + co];
            }
            g_tw[conv][cat][co] = ssum;
        }
    }
    // ---- init y ----
    for (int q=gt; q<NQ; q+=gstride){
        float4 v = ((const float4*)x)[q];
        ((float4*)g_yf[0])[q] = v;
        h_store4(g_yh[0], q*4, v);
    }
    __syncthreads();
    prefetch_w01(sb, g_wh[0], tid);    // W0,W1 for the very first conv1
    gsync();

    // ---- per-CTA solver state (identical in every CTA) ----
    float t = 0.f, dt = 0.05f;
    int cur = 0, done = 0;
    const float TC[7] = {0.f, 0.2f, 0.3f, 0.8f, (float)(8.0/9.0), 1.f, 1.f};

    for (int it=0; it<MAX_STEPS; ++it){
        if (done) break;
        const float dtc = fminf(dt, 1.0f - t);
        for (int s=0; s<7; ++s){
            const float tval = t + TC[s]*dtc;
            conv_phase<0>(dsm, sb, bid, s, b1, dtc, tval, cur, sd, s==0);   // h
            __syncthreads();
            prefetch_w01(sb, g_wh[1], tid);     // conv2's W0,W1 stream during barrier
            gsync();
            conv_phase<1>(dsm, sb, bid, s, b2, dtc, tval, cur, sd, 0);      // k_s (+fused)
            __syncthreads();
            prefetch_w01(sb, g_wh[0], tid);     // next conv1's W0,W1
            gsync();
        }
        // ---- controller, computed redundantly & identically in every CTA ----
        {
            double v=0.0;
            for (int i=tid; i<NTILE; i+=NTHREADS) v += __ldcg(&g_part[i]);
            sd[tid]=v; __syncthreads();
            for (int o=256; o>0; o>>=1){ if (tid<o) sd[tid]+=sd[tid+o]; __syncthreads(); }
            float err_norm = sqrtf((float)(sd[0] / (double)NTOT));
            __syncthreads();
            err_norm = fmaxf(err_norm, 1e-10f);
            int accept = (err_norm <= 1.0f) ? 1 : 0;
            float factor = 0.9f * powf(err_norm, -0.2f);
            factor = fminf(fmaxf(factor, 0.2f), 10.0f);
            if (accept){ t += dtc; cur ^= 1; }
            dt = dtc * factor;
            if (t >= 1.0f - 1e-6f) done = 1;
        }
    }

    // ---- final copy ----
    for (int q=gt; q<NQ; q+=gstride)
        ((float4*)out)[q] = __ldcg((const float4*)g_yf[cur] + q);
}

// ============ launch ============
extern "C" void kernel_launch(void* const* d_in, const int* in_sizes, int n_in,
                              void* d_out, int out_size){
    const float* x = 0; const float* w[2] = {0,0}; const float* b[2] = {0,0};
    int nw=0, nb_=0;
    for (int i=0;i<n_in;i++){
        if (in_sizes[i] == NTOT) x = (const float*)d_in[i];
        else if (in_sizes[i] == WSIZE){ if (nw<2) w[nw++] = (const float*)d_in[i]; }
        else if (in_sizes[i] == CH){ if (nb_<2) b[nb_++] = (const float*)d_in[i]; }
    }
    cudaFuncSetAttribute(k_solver, cudaFuncAttributeMaxDynamicSharedMemorySize, CONV_SMEM);
    cudaFuncSetAttribute(k_solver, cudaFuncAttributePreferredSharedMemoryCarveout, 100);
    k_solver<<<GRID, NTHREADS, CONV_SMEM>>>(x, w[0], b[0], w[1], b[1], (float*)d_out);
}

// round 16
// speedup vs baseline: 1.7144x; 1.0217x over previous
#include <cuda_runtime.h>
#include <cuda_fp16.h>
#include <stdint.h>
#include <math.h>

#define CH 128
#define NPIX 32768              // 32*32*32
#define NTOT (NPIX*CH)          // 4194304
#define NQ (NTOT/4)
#define WSIZE (3*3*129*128)
#define NWB (9*128*128)         // 147456
#define MAX_STEPS 32
#define GRID 128
#define NTHREADS 512
#define NTILE 128               // tiles of 256 pixels

// ---- Dormand-Prince coefficients ----
#define C10 0.2f
#define C20 ((float)(3.0/40.0))
#define C21 ((float)(9.0/40.0))
#define C30 ((float)(44.0/45.0))
#define C31 ((float)(-56.0/15.0))
#define C32 ((float)(32.0/9.0))
#define C40 ((float)(19372.0/6561.0))
#define C41 ((float)(-25360.0/2187.0))
#define C42 ((float)(64448.0/6561.0))
#define C43 ((float)(-212.0/729.0))
#define C50 ((float)(9017.0/3168.0))
#define C51 ((float)(-355.0/33.0))
#define C52 ((float)(46732.0/5247.0))
#define C53 ((float)(49.0/176.0))
#define C54 ((float)(-5103.0/18656.0))
#define B0c ((float)(35.0/384.0))
#define B2c ((float)(500.0/1113.0))
#define B3c ((float)(125.0/192.0))
#define B4c ((float)(-2187.0/6784.0))
#define B5c ((float)(11.0/84.0))
#define E0c ((float)(35.0/384.0 - 5179.0/57600.0))
#define E2c ((float)(500.0/1113.0 - 7571.0/16695.0))
#define E3c ((float)(125.0/192.0 - 393.0/640.0))
#define E4c ((float)(-2187.0/6784.0 + 92097.0/339200.0))
#define E5c ((float)(11.0/84.0 - 187.0/2100.0))
#define E6c ((float)(-1.0/40.0))

// ---- Persistent state ----
__device__ __align__(16) float g_yf[2][NTOT];        // ping-pong fp32 y ([cur^1] holds y5)
__device__ __align__(16) float g_k[7][NTOT];
__device__ __align__(16) __half g_yh[2][NTOT];       // fp16 mirrors
__device__ __align__(16) __half g_tmph[NTOT];
__device__ __align__(16) __half g_hh[NTOT];
__device__ __align__(16) __half g_wh[2][NWB];        // [conv][tap*16384 + co*128 + ci]
__device__ float g_tw[2][9][128];
__device__ double g_part[NTILE];
__device__ unsigned g_arrive, g_gen;                 // grid barrier (zero-init)
__device__ unsigned g_pc[NTILE];                     // per-tile phase counters (zero-init)

// ---- conv smem layout ----
#define A_ROWB 272
#define A_ENT  340               // 10*34
#define A_BYTES (A_ENT*A_ROWB)   // 92480
#define W_ROWB 272
#define W_STG  (128*W_ROWB)      // 34816
#define W_RING A_BYTES
#define CONV_SMEM (A_BYTES + 3*W_STG)   // 196928
#define STG_ROWB 272

// ============ PTX wrappers (base ISA, valid for compute_103) ============
__device__ __forceinline__ uint32_t smem_u32(const void* p){
    uint32_t a;
    asm("{ .reg .u64 t; cvta.to.shared.u64 t, %1; cvt.u32.u64 %0, t; }" : "=r"(a) : "l"(p));
    return a;
}
__device__ __forceinline__ void cpa16(uint32_t dst, const void* src, uint32_t sz){
    asm volatile("cp.async.cg.shared.global [%0], [%1], 16, %2;" :: "r"(dst), "l"(src), "r"(sz));
}
#define CP_COMMIT() asm volatile("cp.async.commit_group;" ::: "memory")
#define CP_WAIT1()  asm volatile("cp.async.wait_group 1;" ::: "memory")
#define CP_WAIT0()  asm volatile("cp.async.wait_group 0;" ::: "memory")

__device__ __forceinline__ void ldm4(uint32_t* r, uint32_t addr){
    asm volatile("ldmatrix.sync.aligned.m8n8.x4.shared.b16 {%0,%1,%2,%3}, [%4];"
        : "=r"(r[0]), "=r"(r[1]), "=r"(r[2]), "=r"(r[3]) : "r"(addr));
}
__device__ __forceinline__ void mma16816(float* c, const uint32_t* a, uint32_t b0, uint32_t b1){
    asm volatile("mma.sync.aligned.m16n8k16.row.col.f32.f16.f16.f32 "
        "{%0,%1,%2,%3}, {%4,%5,%6,%7}, {%8,%9}, {%0,%1,%2,%3};"
        : "+f"(c[0]), "+f"(c[1]), "+f"(c[2]), "+f"(c[3])
        : "r"(a[0]), "r"(a[1]), "r"(a[2]), "r"(a[3]), "r"(b0), "r"(b1));
}
__device__ __forceinline__ uint32_t pk2h(__half a, __half b){
    return (uint32_t)__half_as_ushort(a) | ((uint32_t)__half_as_ushort(b) << 16);
}
__device__ __forceinline__ void h_store4(__half* Hp, int e, float4 v){
    uint2 H = make_uint2(pk2h(__float2half(v.x), __float2half(v.y)),
                         pk2h(__float2half(v.z), __float2half(v.w)));
    *(uint2*)(Hp + e) = H;
}

// ---- grid-wide sense barrier (all GRID CTAs resident) ----
__device__ __forceinline__ void gsync(){
    __threadfence();
    __syncthreads();
    if (threadIdx.x == 0){
        unsigned g;
        asm volatile("ld.acquire.gpu.u32 %0, [%1];" : "=r"(g) : "l"(&g_gen));
        unsigned old;
        asm volatile("atom.add.release.gpu.u32 %0, [%1], 1;" : "=r"(old) : "l"(&g_arrive) : "memory");
        if (old == GRID-1){
            asm volatile("st.relaxed.gpu.u32 [%0], 0;" :: "l"(&g_arrive) : "memory");
            asm volatile("st.release.gpu.u32 [%0], %1;" :: "l"(&g_gen), "r"(g+1) : "memory");
        } else {
            unsigned cur;
            do {
                __nanosleep(64);
                asm volatile("ld.acquire.gpu.u32 %0, [%1];" : "=r"(cur) : "l"(&g_gen));
            } while (cur == g);
        }
    }
    __syncthreads();
}

// ---- neighbor-only synchronization (tiles ±1 within same image) ----
__device__ __forceinline__ unsigned ld_acq(const unsigned* p){
    unsigned v; asm volatile("ld.acquire.gpu.u32 %0, [%1];" : "=r"(v) : "l"(p)); return v;
}
// wait until both existing neighbors have completed >= P phases
__device__ __forceinline__ void nb_wait(int tile, unsigned P){
    if (threadIdx.x == 0 && (tile & 3) != 0){
        while (ld_acq(&g_pc[tile-1]) < P) __nanosleep(32);
    }
    if (threadIdx.x == 32 && (tile & 3) != 3){
        while (ld_acq(&g_pc[tile+1]) < P) __nanosleep(32);
    }
    __syncthreads();
}
// publish completion of phase (counter -> P1) after epilogue writes
__device__ __forceinline__ void publish(int tile, unsigned P1){
    __threadfence();
    __syncthreads();
    if (threadIdx.x == 0)
        asm volatile("st.release.gpu.u32 [%0], %1;" :: "l"(&g_pc[tile]), "r"(P1) : "memory");
}

#define LDK4(j) __ldcg((const float4*)(g_k[j]+idx))

// ---- prefetch W chunks 0,1 for the NEXT phase (weights immutable) ----
__device__ __forceinline__ void prefetch_w01(uint32_t sb, const __half* __restrict__ Wg, int tid){
    #pragma unroll
    for (int st=0; st<2; ++st){
        const uint32_t base = sb + W_RING + st*W_STG;
        const int wbase = st*16384;
        #pragma unroll
        for (int j=0;j<4;j++){
            int sl = tid + j*NTHREADS;
            int row = sl >> 4, seg = sl & 15;
            cpa16(base + (uint32_t)(row*W_ROWB + seg*16), Wg + (wbase + row*128 + seg*8), 16u);
        }
        CP_COMMIT();
    }
}

// ============ conv phase: CTA tile 256pix x 128co; 16 warps, warp tile 32x64 ============
template<int WSEL>
__device__ __forceinline__ void conv_phase(
    char* dsm, uint32_t sb, int tile, int s,
    const float* __restrict__ Bias, float dtc, float tval, int cur,
    double* sdErr, int fullA)
{
    const int tid  = threadIdx.x;
    const int wid  = tid >> 5;
    const int lane = tid & 31;

    const __half* __restrict__ X = (WSEL==0) ? ((s==0) ? g_yh[cur] : g_tmph) : g_hh;
    const __half* __restrict__ Wg = g_wh[WSEL];

    const int n_img = tile >> 2;
    const int h0 = (tile & 3) << 3;          // first owned image row (8 rows per tile)
    const __half* Xi = X + ((long)n_img << 17);   // 32*32*128 per image

    if (fullA){
        #pragma unroll
        for (int j=0; j<11; ++j){
            int sl = tid + j*NTHREADS;
            if (sl < A_ENT*16){
                int e = sl >> 4, seg = sl & 15;
                int hr = e / 34, wc = e - hr*34;
                int gr = h0 + hr - 1, gw = wc - 1;
                bool v = ((unsigned)gr < 32u) && ((unsigned)gw < 32u);
                long off = v ? (((long)(gr*32 + gw)) << 7) + seg*8 : 0;
                cpa16(sb + (uint32_t)(e*A_ROWB + seg*16), Xi + off, v ? 16u : 0u);
            }
        }
    } else {
        // halo only: rows hr=0 and hr=9 (34 entries each) + side columns rows 1..8 (16)
        #pragma unroll
        for (int j=0; j<3; ++j){
            int sl = tid + j*NTHREADS;
            if (sl < 84*16){
                int ei = sl >> 4, seg = sl & 15;
                int hr, wc;
                if (ei < 34){ hr = 0; wc = ei; }
                else if (ei < 68){ hr = 9; wc = ei - 34; }
                else { int k = ei - 68; hr = 1 + (k >> 1); wc = (k & 1) ? 33 : 0; }
                int e = hr*34 + wc;
                int gr = h0 + hr - 1, gw = wc - 1;
                bool v = ((unsigned)gr < 32u) && ((unsigned)gw < 32u);
                long off = v ? (((long)(gr*32 + gw)) << 7) + seg*8 : 0;
                cpa16(sb + (uint32_t)(e*A_ROWB + seg*16), Xi + off, v ? 16u : 0u);
            }
        }
    }
    CP_COMMIT();

    auto load_w = [&](int tap, int st){
        const uint32_t base = sb + W_RING + st*W_STG;
        const int wbase = tap*16384;
        #pragma unroll
        for (int j=0;j<4;j++){
            int sl = tid + j*NTHREADS;
            int row = sl >> 4, seg = sl & 15;
            cpa16(base + (uint32_t)(row*W_ROWB + seg*16), Wg + (wbase + row*128 + seg*8), 16u);
        }
    };

    const int m0 = (wid & 7) * 32;
    const int n0 = (wid >> 3) * 64;
    uint32_t abase[2];
    #pragma unroll
    for (int mt=0; mt<2; ++mt){
        int px = m0 + (lane & 15) + mt*16;
        int lr = px >> 5, w = px & 31;
        abase[mt] = (uint32_t)(((lr+1)*34 + (w+1))*A_ROWB + (lane >> 4)*16);
    }
    const uint32_t boffbase = (uint32_t)((n0 + (lane & 7) + ((lane >> 4) << 3))*W_ROWB + ((lane >> 3) & 1)*16);

    float acc[2][8][4];
    #pragma unroll
    for (int i=0;i<2;i++)
        #pragma unroll
        for (int j=0;j<8;j++)
            #pragma unroll
            for (int q=0;q<4;q++) acc[i][j][q]=0.f;

    // groups outstanding at entry: W0, W1 (prefetched pre-wait), A/halo (just committed)
    #pragma unroll 1
    for (int c=0; c<9; ++c){
        if (c==0 || c==8) CP_WAIT0(); else CP_WAIT1();
        __syncthreads();
        if (c<7){ load_w(c+2, (c+2)%3); CP_COMMIT(); }

        const int dh = c/3 - 1, dw = c - (c/3)*3 - 1;
        const uint32_t ashift = (uint32_t)((dh*34 + dw)*A_ROWB);
        const uint32_t aoff0 = sb + abase[0] + ashift;
        const uint32_t aoff1 = sb + abase[1] + ashift;
        const uint32_t boff = sb + W_RING + (c%3)*W_STG + boffbase;
        #pragma unroll
        for (int k16=0; k16<8; ++k16){
            const uint32_t kb = (uint32_t)(k16*32);
            uint32_t a0[4], a1[4];
            ldm4(a0, aoff0 + kb);
            ldm4(a1, aoff1 + kb);
            #pragma unroll
            for (int nt=0;nt<4;nt++){
                uint32_t b[4];
                ldm4(b, boff + (uint32_t)(nt*16*W_ROWB) + kb);
                mma16816(acc[0][2*nt],   a0, b[0], b[1]);
                mma16816(acc[0][2*nt+1], a0, b[2], b[3]);
                mma16816(acc[1][2*nt],   a1, b[0], b[1]);
                mma16816(acc[1][2*nt+1], a1, b[2], b[3]);
            }
        }
    }

    // ---- epilogue: stage fragments through smem, then coalesced global I/O ----
    const int mglob = tile*256;
    char* stg = dsm + W_RING;
    double errsum = 0.0;

    #pragma unroll 1
    for (int nh=0; nh<2; ++nh){
        __syncthreads();
        if ((wid >> 3) == nh){
            const int gID = lane >> 2, tq = lane & 3;
            #pragma unroll
            for (int mt=0; mt<2; ++mt)
                #pragma unroll
                for (int rr=0; rr<2; ++rr){
                    int row = m0 + mt*16 + rr*8 + gID;
                    #pragma unroll
                    for (int nf=0; nf<8; ++nf)
                        *(float2*)(stg + row*STG_ROWB + (nf*8 + tq*2)*4) =
                            make_float2(acc[mt][nf][rr*2], acc[mt][nf][rr*2+1]);
                }
        }
        __syncthreads();
        #pragma unroll 1
        for (int j=0; j<8; ++j){
            int sl = tid + j*NTHREADS;
            int row = sl >> 4, seg = sl & 15;
            float4 a = *(const float4*)(stg + row*STG_ROWB + seg*16);
            int col = nh*64 + seg*4;
            int m = mglob + row;
            int hp = (m >> 5) & 31, wp = m & 31;
            int cat = ((hp==0)?0:(hp==31)?6:3) + ((wp==0)?0:(wp==31)?2:1);
            float4 tw4 = *(const float4*)(g_tw[WSEL][cat] + col);
            float4 b4  = *(const float4*)(Bias + col);
            float4 v;
            v.x = fmaxf(a.x + tval*tw4.x + b4.x, 0.f);
            v.y = fmaxf(a.y + tval*tw4.y + b4.y, 0.f);
            v.z = fmaxf(a.z + tval*tw4.z + b4.z, 0.f);
            v.w = fmaxf(a.w + tval*tw4.w + b4.w, 0.f);
            int idx = m*128 + col;
            const int lr = row >> 5, w = row & 31;
            const uint32_t ae = (uint32_t)(((lr+1)*34 + (w+1))*A_ROWB) + (uint32_t)(col*2);
            if (WSEL==0){
                uint2 pk = make_uint2(pk2h(__float2half(v.x), __float2half(v.y)),
                                      pk2h(__float2half(v.z), __float2half(v.w)));
                *(uint2*)(g_hh + idx) = pk;
                *(uint2*)(dsm + ae) = pk;        // h -> conv2's A
            } else {
                *(float4*)(g_k[s] + idx) = v;
                if (s <= 5){
                    float4 y = __ldcg((const float4*)(g_yf[cur] + idx));
                    float4 c4;
                    if (s==0){
                        c4.x = C10*v.x; c4.y = C10*v.y; c4.z = C10*v.z; c4.w = C10*v.w;
                    } else if (s==1){
                        float4 k0=LDK4(0);
                        c4.x = C20*k0.x + C21*v.x; c4.y = C20*k0.y + C21*v.y;
                        c4.z = C20*k0.z + C21*v.z; c4.w = C20*k0.w + C21*v.w;
                    } else if (s==2){
                        float4 k0=LDK4(0), k1=LDK4(1);
                        c4.x = C30*k0.x + C31*k1.x + C32*v.x;
                        c4.y = C30*k0.y + C31*k1.y + C32*v.y;
                        c4.z = C30*k0.z + C31*k1.z + C32*v.z;
                        c4.w = C30*k0.w + C31*k1.w + C32*v.w;
                    } else if (s==3){
                        float4 k0=LDK4(0), k1=LDK4(1), k2=LDK4(2);
                        c4.x = C40*k0.x + C41*k1.x + C42*k2.x + C43*v.x;
                        c4.y = C40*k0.y + C41*k1.y + C42*k2.y + C43*v.y;
                        c4.z = C40*k0.z + C41*k1.z + C42*k2.z + C43*v.z;
                        c4.w = C40*k0.w + C41*k1.w + C42*k2.w + C43*v.w;
                    } else if (s==4){
                        float4 k0=LDK4(0), k1=LDK4(1), k2=LDK4(2), k3=LDK4(3);
                        c4.x = C50*k0.x + C51*k1.x + C52*k2.x + C53*k3.x + C54*v.x;
                        c4.y = C50*k0.y + C51*k1.y + C52*k2.y + C53*k3.y + C54*v.y;
                        c4.z = C50*k0.z + C51*k1.z + C52*k2.z + C53*k3.z + C54*v.z;
                        c4.w = C50*k0.w + C51*k1.w + C52*k2.w + C53*k3.w + C54*v.w;
                    } else {
                        float4 k0=LDK4(0), k2=LDK4(2), k3=LDK4(3), k4=LDK4(4);
                        c4.x = B0c*k0.x + B2c*k2.x + B3c*k3.x + B4c*k4.x + B5c*v.x;
                        c4.y = B0c*k0.y + B2c*k2.y + B3c*k3.y + B4c*k4.y + B5c*v.y;
                        c4.z = B0c*k0.z + B2c*k2.z + B3c*k3.z + B4c*k4.z + B5c*v.z;
                        c4.w = B0c*k0.w + B2c*k2.w + B3c*k3.w + B4c*k4.w + B5c*v.w;
                    }
                    float4 tv;
                    tv.x = y.x + dtc*c4.x; tv.y = y.y + dtc*c4.y;
                    tv.z = y.z + dtc*c4.z; tv.w = y.w + dtc*c4.w;
                    uint2 pk = make_uint2(pk2h(__float2half(tv.x), __float2half(tv.y)),
                                          pk2h(__float2half(tv.z), __float2half(tv.w)));
                    *(uint2*)(g_tmph + idx) = pk;
                    *(uint2*)(dsm + ae) = pk;    // tmp -> next conv1's A
                    if (s==5){
                        *(float4*)(g_yf[cur^1] + idx) = tv;
                        *(uint2*)(g_yh[cur^1] + idx) = pk;
                    }
                } else {
                    float4 k0=LDK4(0), k2=LDK4(2), k3=LDK4(3), k4=LDK4(4), k5=LDK4(5);
                    float4 y  = __ldcg((const float4*)(g_yf[cur]   + idx));
                    float4 y5 = __ldcg((const float4*)(g_yf[cur^1] + idx));
                    float e0 = dtc*(E0c*k0.x + E2c*k2.x + E3c*k3.x + E4c*k4.x + E5c*k5.x + E6c*v.x);
                    float e1 = dtc*(E0c*k0.y + E2c*k2.y + E3c*k3.y + E4c*k4.y + E5c*k5.y + E6c*v.y);
                    float e2 = dtc*(E0c*k0.z + E2c*k2.z + E3c*k3.z + E4c*k4.z + E5c*k5.z + E6c*v.z);
                    float e3 = dtc*(E0c*k0.w + E2c*k2.w + E3c*k3.w + E4c*k4.w + E5c*k5.w + E6c*v.w);
                    float sc0 = 1e-3f + 1e-3f*fmaxf(fabsf(y.x), fabsf(y5.x));
                    float sc1 = 1e-3f + 1e-3f*fmaxf(fabsf(y.y), fabsf(y5.y));
                    float sc2 = 1e-3f + 1e-3f*fmaxf(fabsf(y.z), fabsf(y5.z));
                    float sc3 = 1e-3f + 1e-3f*fmaxf(fabsf(y.w), fabsf(y5.w));
                    float r0 = e0/sc0, r1 = e1/sc1, r2 = e2/sc2, r3 = e3/sc3;
                    errsum += (double)r0*(double)r0 + (double)r1*(double)r1
                            + (double)r2*(double)r2 + (double)r3*(double)r3;
                }
            }
        }
    }
    if (WSEL==1 && s==6){
        sdErr[tid] = errsum;
        __syncthreads();
        for (int o=256; o>0; o>>=1){
            if (tid < o) sdErr[tid] += sdErr[tid+o];
            __syncthreads();
        }
        if (tid==0) g_part[tile] = sdErr[0];
    }
}

// ============ the single persistent kernel ============
__global__ __launch_bounds__(NTHREADS,1)
void k_solver(const float* __restrict__ x,
              const float* __restrict__ w1, const float* __restrict__ b1,
              const float* __restrict__ w2, const float* __restrict__ b2,
              float* __restrict__ out)
{
    extern __shared__ __align__(16) char dsm[];
    __shared__ double sd[NTHREADS];
    const uint32_t sb = smem_u32(dsm);
    const int bid = blockIdx.x, tid = threadIdx.x;
    const int gt = bid*NTHREADS + tid;
    const int gstride = GRID*NTHREADS;

    // ---- prep: weights (transposed fp16) ----
    for (int i=gt; i<2*NWB; i+=gstride){
        int conv = i / NWB, r = i % NWB;
        int tap = r >> 14, co = (r >> 7) & 127, ci = r & 127;
        float v = (conv ? w2 : w1)[(tap*129 + ci)*128 + co];
        g_wh[conv][r] = __float2half(v);
    }
    // ---- prep: t-channel weight sums per border category ----
    if (bid==0 && tid<256){
        int conv = tid >> 7, co = tid & 127;
        const float* w = conv ? w2 : w1;
        for (int cat=0; cat<9; cat++){
            int hc = cat/3, wc = cat%3;
            float ssum = 0.f;
            for (int tap=0; tap<9; tap++){
                int dh = tap/3 - 1, dw = tap%3 - 1;
                bool okh = !((hc==0 && dh<0) || (hc==2 && dh>0));
                bool okw = !((wc==0 && dw<0) || (wc==2 && dw>0));
                if (okh && okw) ssum += w[(tap*129 + 128)*128 + co];
            }
            g_tw[conv][cat][co] = ssum;
        }
    }
    // ---- init y + phase counters ----
    if (gt < NTILE) g_pc[gt] = 0u;
    for (int q=gt; q<NQ; q+=gstride){
        float4 v = ((const float4*)x)[q];
        ((float4*)g_yf[0])[q] = v;
        h_store4(g_yh[0], q*4, v);
    }
    __syncthreads();
    prefetch_w01(sb, g_wh[0], tid);    // W0,W1 for the very first conv1
    gsync();

    // ---- per-CTA solver state (identical in every CTA) ----
    float t = 0.f, dt = 0.05f;
    int cur = 0, done = 0;
    unsigned P = 0;
    const float TC[7] = {0.f, 0.2f, 0.3f, 0.8f, (float)(8.0/9.0), 1.f, 1.f};

    for (int it=0; it<MAX_STEPS; ++it){
        if (done) break;
        const float dtc = fminf(dt, 1.0f - t);
        for (int s=0; s<7; ++s){
            const float tval = t + TC[s]*dtc;
            nb_wait(bid, P);
            conv_phase<0>(dsm, sb, bid, s, b1, dtc, tval, cur, sd, s==0);   // h
            publish(bid, P+1);
            prefetch_w01(sb, g_wh[1], tid);     // conv2's W0,W1 stream during wait
            nb_wait(bid, P+1);
            conv_phase<1>(dsm, sb, bid, s, b2, dtc, tval, cur, sd, 0);      // k_s (+fused)
            publish(bid, P+2);
            prefetch_w01(sb, g_wh[0], tid);     // next conv1's W0,W1
            P += 2;
        }
        gsync();                                // global: err partials + y commit
        // ---- controller, computed redundantly & identically in every CTA ----
        {
            double v=0.0;
            for (int i=tid; i<NTILE; i+=NTHREADS) v += __ldcg(&g_part[i]);
            sd[tid]=v; __syncthreads();
            for (int o=256; o>0; o>>=1){ if (tid<o) sd[tid]+=sd[tid+o]; __syncthreads(); }
            float err_norm = sqrtf((float)(sd[0] / (double)NTOT));
            __syncthreads();
            err_norm = fmaxf(err_norm, 1e-10f);
            int accept = (err_norm <= 1.0f) ? 1 : 0;
            float factor = 0.9f * powf(err_norm, -0.2f);
            factor = fminf(fmaxf(factor, 0.2f), 10.0f);
            if (accept){ t += dtc; cur ^= 1; }
            dt = dtc * factor;
            if (t >= 1.0f - 1e-6f) done = 1;
        }
    }

    // ---- final copy ----
    for (int q=gt; q<NQ; q+=gstride)
        ((float4*)out)[q] = __ldcg((const float4*)g_yf[cur] + q);
}

// ============ launch ============
extern "C" void kernel_launch(void* const* d_in, const int* in_sizes, int n_in,
                              void* d_out, int out_size){
    const float* x = 0; const float* w[2] = {0,0}; const float* b[2] = {0,0};
    int nw=0, nb_=0;
    for (int i=0;i<n_in;i++){
        if (in_sizes[i] == NTOT) x = (const float*)d_in[i];
        else if (in_sizes[i] == WSIZE){ if (nw<2) w[nw++] = (const float*)d_in[i]; }
        else if (in_sizes[i] == CH){ if (nb_<2) b[nb_++] = (const float*)d_in[i]; }
    }
    cudaFuncSetAttribute(k_solver, cudaFuncAttributeMaxDynamicSharedMemorySize, CONV_SMEM);
    cudaFuncSetAttribute(k_solver, cudaFuncAttributePreferredSharedMemoryCarveout, 100);
    k_solver<<<GRID, NTHREADS, CONV_SMEM>>>(x, w[0], b[0], w[1], b[1], (float*)d_out);
}

// round 17
// speedup vs baseline: 1.7260x; 1.0068x over previous
#include <cuda_runtime.h>
#include <cuda_fp16.h>
#include <stdint.h>
#include <math.h>

#define CH 128
#define NPIX 32768              // 32*32*32
#define NTOT (NPIX*CH)          // 4194304
#define NQ (NTOT/4)
#define WSIZE (3*3*129*128)
#define NWB (9*128*128)         // 147456
#define MAX_STEPS 32
#define GRID 128
#define NTHREADS 512
#define NTILE 128               // tiles of 256 pixels

// ---- Dormand-Prince coefficients ----
#define C10 0.2f
#define C20 ((float)(3.0/40.0))
#define C21 ((float)(9.0/40.0))
#define C30 ((float)(44.0/45.0))
#define C31 ((float)(-56.0/15.0))
#define C32 ((float)(32.0/9.0))
#define C40 ((float)(19372.0/6561.0))
#define C41 ((float)(-25360.0/2187.0))
#define C42 ((float)(64448.0/6561.0))
#define C43 ((float)(-212.0/729.0))
#define C50 ((float)(9017.0/3168.0))
#define C51 ((float)(-355.0/33.0))
#define C52 ((float)(46732.0/5247.0))
#define C53 ((float)(49.0/176.0))
#define C54 ((float)(-5103.0/18656.0))
#define B0c ((float)(35.0/384.0))
#define B2c ((float)(500.0/1113.0))
#define B3c ((float)(125.0/192.0))
#define B4c ((float)(-2187.0/6784.0))
#define B5c ((float)(11.0/84.0))
#define E0c ((float)(35.0/384.0 - 5179.0/57600.0))
#define E2c ((float)(500.0/1113.0 - 7571.0/16695.0))
#define E3c ((float)(125.0/192.0 - 393.0/640.0))
#define E4c ((float)(-2187.0/6784.0 + 92097.0/339200.0))
#define E5c ((float)(11.0/84.0 - 187.0/2100.0))
#define E6c ((float)(-1.0/40.0))

// ---- Persistent state ----
__device__ __align__(16) float g_yf[2][NTOT];        // ping-pong fp32 y ([cur^1] holds y5)
__device__ __align__(16) float g_k[7][NTOT];
__device__ __align__(16) __half g_yh[2][NTOT];       // fp16 mirrors
__device__ __align__(16) __half g_tmph[NTOT];        // only boundary rows are ever valid/used
__device__ __align__(16) __half g_hh[NTOT];          // only boundary rows are ever valid/used
__device__ __align__(16) __half g_wh[2][NWB];        // [conv][tap*16384 + co*128 + ci]
__device__ float g_tw[2][9][128];
__device__ double g_part[NTILE];
__device__ unsigned g_arrive, g_gen;                 // grid barrier (zero-init)
__device__ unsigned g_pc[NTILE];                     // per-tile phase counters (zero-init)

// ---- conv smem layout ----
#define A_ROWB 272
#define A_ENT  340               // 10*34
#define A_BYTES (A_ENT*A_ROWB)   // 92480
#define W_ROWB 272
#define W_STG  (128*W_ROWB)      // 34816
#define W_RING A_BYTES
#define CONV_SMEM (A_BYTES + 3*W_STG)   // 196928
#define STG_ROWB 272

// ============ PTX wrappers (base ISA, valid for compute_103) ============
__device__ __forceinline__ uint32_t smem_u32(const void* p){
    uint32_t a;
    asm("{ .reg .u64 t; cvta.to.shared.u64 t, %1; cvt.u32.u64 %0, t; }" : "=r"(a) : "l"(p));
    return a;
}
__device__ __forceinline__ void cpa16(uint32_t dst, const void* src, uint32_t sz){
    asm volatile("cp.async.cg.shared.global [%0], [%1], 16, %2;" :: "r"(dst), "l"(src), "r"(sz));
}
#define CP_COMMIT() asm volatile("cp.async.commit_group;" ::: "memory")
#define CP_WAIT1()  asm volatile("cp.async.wait_group 1;" ::: "memory")
#define CP_WAIT0()  asm volatile("cp.async.wait_group 0;" ::: "memory")

__device__ __forceinline__ void ldm4(uint32_t* r, uint32_t addr){
    asm volatile("ldmatrix.sync.aligned.m8n8.x4.shared.b16 {%0,%1,%2,%3}, [%4];"
        : "=r"(r[0]), "=r"(r[1]), "=r"(r[2]), "=r"(r[3]) : "r"(addr));
}
__device__ __forceinline__ void mma16816(float* c, const uint32_t* a, uint32_t b0, uint32_t b1){
    asm volatile("mma.sync.aligned.m16n8k16.row.col.f32.f16.f16.f32 "
        "{%0,%1,%2,%3}, {%4,%5,%6,%7}, {%8,%9}, {%0,%1,%2,%3};"
        : "+f"(c[0]), "+f"(c[1]), "+f"(c[2]), "+f"(c[3])
        : "r"(a[0]), "r"(a[1]), "r"(a[2]), "r"(a[3]), "r"(b0), "r"(b1));
}
__device__ __forceinline__ uint32_t pk2h(__half a, __half b){
    return (uint32_t)__half_as_ushort(a) | ((uint32_t)__half_as_ushort(b) << 16);
}
__device__ __forceinline__ void h_store4(__half* Hp, int e, float4 v){
    uint2 H = make_uint2(pk2h(__float2half(v.x), __float2half(v.y)),
                         pk2h(__float2half(v.z), __float2half(v.w)));
    *(uint2*)(Hp + e) = H;
}

// ---- grid-wide sense barrier (all GRID CTAs resident) ----
__device__ __forceinline__ void gsync(){
    __threadfence();
    __syncthreads();
    if (threadIdx.x == 0){
        unsigned g;
        asm volatile("ld.acquire.gpu.u32 %0, [%1];" : "=r"(g) : "l"(&g_gen));
        unsigned old;
        asm volatile("atom.add.release.gpu.u32 %0, [%1], 1;" : "=r"(old) : "l"(&g_arrive) : "memory");
        if (old == GRID-1){
            asm volatile("st.relaxed.gpu.u32 [%0], 0;" :: "l"(&g_arrive) : "memory");
            asm volatile("st.release.gpu.u32 [%0], %1;" :: "l"(&g_gen), "r"(g+1) : "memory");
        } else {
            unsigned cur;
            do {
                __nanosleep(64);
                asm volatile("ld.acquire.gpu.u32 %0, [%1];" : "=r"(cur) : "l"(&g_gen));
            } while (cur == g);
        }
    }
    __syncthreads();
}

// ---- neighbor-only synchronization (tiles ±1 within same image) ----
__device__ __forceinline__ unsigned ld_acq(const unsigned* p){
    unsigned v; asm volatile("ld.acquire.gpu.u32 %0, [%1];" : "=r"(v) : "l"(p)); return v;
}
__device__ __forceinline__ void nb_wait(int tile, unsigned P){
    if (threadIdx.x == 0 && (tile & 3) != 0){
        while (ld_acq(&g_pc[tile-1]) < P) __nanosleep(32);
    }
    if (threadIdx.x == 32 && (tile & 3) != 3){
        while (ld_acq(&g_pc[tile+1]) < P) __nanosleep(32);
    }
    __syncthreads();
}
__device__ __forceinline__ void publish(int tile, unsigned P1){
    __threadfence();
    __syncthreads();
    if (threadIdx.x == 0)
        asm volatile("st.release.gpu.u32 [%0], %1;" :: "l"(&g_pc[tile]), "r"(P1) : "memory");
}

#define LDK4(j) __ldcg((const float4*)(g_k[j]+idx))

// ---- prefetch W chunks 0,1 for the NEXT phase (weights immutable) ----
__device__ __forceinline__ void prefetch_w01(uint32_t sb, const __half* __restrict__ Wg, int tid){
    #pragma unroll
    for (int st=0; st<2; ++st){
        const uint32_t base = sb + W_RING + st*W_STG;
        const int wbase = st*16384;
        #pragma unroll
        for (int j=0;j<4;j++){
            int sl = tid + j*NTHREADS;
            int row = sl >> 4, seg = sl & 15;
            cpa16(base + (uint32_t)(row*W_ROWB + seg*16), Wg + (wbase + row*128 + seg*8), 16u);
        }
        CP_COMMIT();
    }
}

// ============ conv phase: CTA tile 256pix x 128co; 16 warps, warp tile 32x64 ============
template<int WSEL>
__device__ __forceinline__ void conv_phase(
    char* dsm, uint32_t sb, int tile, int s,
    const float* __restrict__ Bias, float dtc, float tval, int cur,
    double* sdErr, int fullA)
{
    const int tid  = threadIdx.x;
    const int wid  = tid >> 5;
    const int lane = tid & 31;

    // conv1 input: y (s=0), y5 (s=6; == tmp at s=5), else tmp. conv2 input: h.
    const __half* __restrict__ X = (WSEL==0)
        ? ((s==0) ? g_yh[cur] : ((s==6) ? g_yh[cur^1] : g_tmph))
        : g_hh;
    const __half* __restrict__ Wg = g_wh[WSEL];

    const int n_img = tile >> 2;
    const int h0 = (tile & 3) << 3;          // first owned image row (8 rows per tile)
    const __half* Xi = X + ((long)n_img << 17);   // 32*32*128 per image

    if (fullA){
        #pragma unroll
        for (int j=0; j<11; ++j){
            int sl = tid + j*NTHREADS;
            if (sl < A_ENT*16){
                int e = sl >> 4, seg = sl & 15;
                int hr = e / 34, wc = e - hr*34;
                int gr = h0 + hr - 1, gw = wc - 1;
                bool v = ((unsigned)gr < 32u) && ((unsigned)gw < 32u);
                long off = v ? (((long)(gr*32 + gw)) << 7) + seg*8 : 0;
                cpa16(sb + (uint32_t)(e*A_ROWB + seg*16), Xi + off, v ? 16u : 0u);
            }
        }
    } else {
        // halo only: rows hr=0 and hr=9 (34 entries each) + side columns rows 1..8 (16)
        #pragma unroll
        for (int j=0; j<3; ++j){
            int sl = tid + j*NTHREADS;
            if (sl < 84*16){
                int ei = sl >> 4, seg = sl & 15;
                int hr, wc;
                if (ei < 34){ hr = 0; wc = ei; }
                else if (ei < 68){ hr = 9; wc = ei - 34; }
                else { int k = ei - 68; hr = 1 + (k >> 1); wc = (k & 1) ? 33 : 0; }
                int e = hr*34 + wc;
                int gr = h0 + hr - 1, gw = wc - 1;
                bool v = ((unsigned)gr < 32u) && ((unsigned)gw < 32u);
                long off = v ? (((long)(gr*32 + gw)) << 7) + seg*8 : 0;
                cpa16(sb + (uint32_t)(e*A_ROWB + seg*16), Xi + off, v ? 16u : 0u);
            }
        }
    }
    CP_COMMIT();

    auto load_w = [&](int tap, int st){
        const uint32_t base = sb + W_RING + st*W_STG;
        const int wbase = tap*16384;
        #pragma unroll
        for (int j=0;j<4;j++){
            int sl = tid + j*NTHREADS;
            int row = sl >> 4, seg = sl & 15;
            cpa16(base + (uint32_t)(row*W_ROWB + seg*16), Wg + (wbase + row*128 + seg*8), 16u);
        }
    };

    const int m0 = (wid & 7) * 32;
    const int n0 = (wid >> 3) * 64;
    uint32_t abase[2];
    #pragma unroll
    for (int mt=0; mt<2; ++mt){
        int px = m0 + (lane & 15) + mt*16;
        int lr = px >> 5, w = px & 31;
        abase[mt] = (uint32_t)(((lr+1)*34 + (w+1))*A_ROWB + (lane >> 4)*16);
    }
    const uint32_t boffbase = (uint32_t)((n0 + (lane & 7) + ((lane >> 4) << 3))*W_ROWB + ((lane >> 3) & 1)*16);

    float acc[2][8][4];
    #pragma unroll
    for (int i=0;i<2;i++)
        #pragma unroll
        for (int j=0;j<8;j++)
            #pragma unroll
            for (int q=0;q<4;q++) acc[i][j][q]=0.f;

    // groups outstanding at entry: W0, W1 (prefetched pre-wait), A/halo (just committed)
    #pragma unroll 1
    for (int c=0; c<9; ++c){
        if (c==0 || c==8) CP_WAIT0(); else CP_WAIT1();
        __syncthreads();
        if (c<7){ load_w(c+2, (c+2)%3); CP_COMMIT(); }

        const int dh = c/3 - 1, dw = c - (c/3)*3 - 1;
        const uint32_t ashift = (uint32_t)((dh*34 + dw)*A_ROWB);
        const uint32_t aoff0 = sb + abase[0] + ashift;
        const uint32_t aoff1 = sb + abase[1] + ashift;
        const uint32_t boff = sb + W_RING + (c%3)*W_STG + boffbase;
        #pragma unroll
        for (int k16=0; k16<8; ++k16){
            const uint32_t kb = (uint32_t)(k16*32);
            uint32_t a0[4], a1[4];
            ldm4(a0, aoff0 + kb);
            ldm4(a1, aoff1 + kb);
            #pragma unroll
            for (int nt=0;nt<4;nt++){
                uint32_t b[4];
                ldm4(b, boff + (uint32_t)(nt*16*W_ROWB) + kb);
                mma16816(acc[0][2*nt],   a0, b[0], b[1]);
                mma16816(acc[0][2*nt+1], a0, b[2], b[3]);
                mma16816(acc[1][2*nt],   a1, b[0], b[1]);
                mma16816(acc[1][2*nt+1], a1, b[2], b[3]);
            }
        }
    }

    // ---- epilogue: stage fragments through smem, then coalesced global I/O ----
    const int mglob = tile*256;
    char* stg = dsm + W_RING;
    double errsum = 0.0;

    #pragma unroll 1
    for (int nh=0; nh<2; ++nh){
        __syncthreads();
        if ((wid >> 3) == nh){
            const int gID = lane >> 2, tq = lane & 3;
            #pragma unroll
            for (int mt=0; mt<2; ++mt)
                #pragma unroll
                for (int rr=0; rr<2; ++rr){
                    int row = m0 + mt*16 + rr*8 + gID;
                    #pragma unroll
                    for (int nf=0; nf<8; ++nf)
                        *(float2*)(stg + row*STG_ROWB + (nf*8 + tq*2)*4) =
                            make_float2(acc[mt][nf][rr*2], acc[mt][nf][rr*2+1]);
                }
        }
        __syncthreads();
        #pragma unroll 1
        for (int j=0; j<8; ++j){
            int sl = tid + j*NTHREADS;
            int row = sl >> 4, seg = sl & 15;
            float4 a = *(const float4*)(stg + row*STG_ROWB + seg*16);
            int col = nh*64 + seg*4;
            int m = mglob + row;
            int hp = (m >> 5) & 31, wp = m & 31;
            int cat = ((hp==0)?0:(hp==31)?6:3) + ((wp==0)?0:(wp==31)?2:1);
            float4 tw4 = *(const float4*)(g_tw[WSEL][cat] + col);
            float4 b4  = *(const float4*)(Bias + col);
            float4 v;
            v.x = fmaxf(a.x + tval*tw4.x + b4.x, 0.f);
            v.y = fmaxf(a.y + tval*tw4.y + b4.y, 0.f);
            v.z = fmaxf(a.z + tval*tw4.z + b4.z, 0.f);
            v.w = fmaxf(a.w + tval*tw4.w + b4.w, 0.f);
            int idx = m*128 + col;
            const int lr = row >> 5, w = row & 31;
            const bool bnd = (lr == 0) || (lr == 7);   // rows neighbors read as halo
            const uint32_t ae = (uint32_t)(((lr+1)*34 + (w+1))*A_ROWB) + (uint32_t)(col*2);
            if (WSEL==0){
                uint2 pk = make_uint2(pk2h(__float2half(v.x), __float2half(v.y)),
                                      pk2h(__float2half(v.z), __float2half(v.w)));
                *(uint2*)(dsm + ae) = pk;             // h -> conv2's A (owned, smem)
                if (bnd) *(uint2*)(g_hh + idx) = pk;  // publish halo rows only
            } else {
                if (s <= 5){
                    *(float4*)(g_k[s] + idx) = v;
                    float4 y = __ldcg((const float4*)(g_yf[cur] + idx));
                    float4 c4;
                    if (s==0){
                        c4.x = C10*v.x; c4.y = C10*v.y; c4.z = C10*v.z; c4.w = C10*v.w;
                    } else if (s==1){
                        float4 k0=LDK4(0);
                        c4.x = C20*k0.x + C21*v.x; c4.y = C20*k0.y + C21*v.y;
                        c4.z = C20*k0.z + C21*v.z; c4.w = C20*k0.w + C21*v.w;
                    } else if (s==2){
                        float4 k0=LDK4(0), k1=LDK4(1);
                        c4.x = C30*k0.x + C31*k1.x + C32*v.x;
                        c4.y = C30*k0.y + C31*k1.y + C32*v.y;
                        c4.z = C30*k0.z + C31*k1.z + C32*v.z;
                        c4.w = C30*k0.w + C31*k1.w + C32*v.w;
                    } else if (s==3){
                        float4 k0=LDK4(0), k1=LDK4(1), k2=LDK4(2);
                        c4.x = C40*k0.x + C41*k1.x + C42*k2.x + C43*v.x;
                        c4.y = C40*k0.y + C41*k1.y + C42*k2.y + C43*v.y;
                        c4.z = C40*k0.z + C41*k1.z + C42*k2.z + C43*v.z;
                        c4.w = C40*k0.w + C41*k1.w + C42*k2.w + C43*v.w;
                    } else if (s==4){
                        float4 k0=LDK4(0), k1=LDK4(1), k2=LDK4(2), k3=LDK4(3);
                        c4.x = C50*k0.x + C51*k1.x + C52*k2.x + C53*k3.x + C54*v.x;
                        c4.y = C50*k0.y + C51*k1.y + C52*k2.y + C53*k3.y + C54*v.y;
                        c4.z = C50*k0.z + C51*k1.z + C52*k2.z + C53*k3.z + C54*v.z;
                        c4.w = C50*k0.w + C51*k1.w + C52*k2.w + C53*k3.w + C54*v.w;
                    } else {
                        float4 k0=LDK4(0), k2=LDK4(2), k3=LDK4(3), k4=LDK4(4);
                        c4.x = B0c*k0.x + B2c*k2.x + B3c*k3.x + B4c*k4.x + B5c*v.x;
                        c4.y = B0c*k0.y + B2c*k2.y + B3c*k3.y + B4c*k4.y + B5c*v.y;
                        c4.z = B0c*k0.z + B2c*k2.z + B3c*k3.z + B4c*k4.z + B5c*v.z;
                        c4.w = B0c*k0.w + B2c*k2.w + B3c*k3.w + B4c*k4.w + B5c*v.w;
                    }
                    float4 tv;
                    tv.x = y.x + dtc*c4.x; tv.y = y.y + dtc*c4.y;
                    tv.z = y.z + dtc*c4.z; tv.w = y.w + dtc*c4.w;
                    uint2 pk = make_uint2(pk2h(__float2half(tv.x), __float2half(tv.y)),
                                          pk2h(__float2half(tv.z), __float2half(tv.w)));
                    *(uint2*)(dsm + ae) = pk;                     // tmp -> next conv1's A
                    if (s < 5){
                        if (bnd) *(uint2*)(g_tmph + idx) = pk;    // halo rows only
                    } else {
                        // s==5: tmp == y5; publish full y5 (fp32 + fp16 mirror)
                        *(float4*)(g_yf[cur^1] + idx) = tv;
                        *(uint2*)(g_yh[cur^1] + idx) = pk;
                    }
                } else {
                    // s==6: no k store (never read); error estimate + A := y5h for next step
                    float4 k0=LDK4(0), k2=LDK4(2), k3=LDK4(3), k4=LDK4(4), k5=LDK4(5);
                    float4 y  = __ldcg((const float4*)(g_yf[cur]   + idx));
                    float4 y5 = __ldcg((const float4*)(g_yf[cur^1] + idx));
                    float e0 = dtc*(E0c*k0.x + E2c*k2.x + E3c*k3.x + E4c*k4.x + E5c*k5.x + E6c*v.x);
                    float e1 = dtc*(E0c*k0.y + E2c*k2.y + E3c*k3.y + E4c*k4.y + E5c*k5.y + E6c*v.y);
                    float e2 = dtc*(E0c*k0.z + E2c*k2.z + E3c*k3.z + E4c*k4.z + E5c*k5.z + E6c*v.z);
                    float e3 = dtc*(E0c*k0.w + E2c*k2.w + E3c*k3.w + E4c*k4.w + E5c*k5.w + E6c*v.w);
                    float sc0 = 1e-3f + 1e-3f*fmaxf(fabsf(y.x), fabsf(y5.x));
                    float sc1 = 1e-3f + 1e-3f*fmaxf(fabsf(y.y), fabsf(y5.y));
                    float sc2 = 1e-3f + 1e-3f*fmaxf(fabsf(y.z), fabsf(y5.z));
                    float sc3 = 1e-3f + 1e-3f*fmaxf(fabsf(y.w), fabsf(y5.w));
                    float r0 = e0/sc0, r1 = e1/sc1, r2 = e2/sc2, r3 = e3/sc3;
                    errsum += (double)r0*(double)r0 + (double)r1*(double)r1
                            + (double)r2*(double)r2 + (double)r3*(double)r3;
                    // A := y5 (fp16) so an ACCEPTED step can skip the s=0 A reload
                    uint2 pk5 = make_uint2(pk2h(__float2half(y5.x), __float2half(y5.y)),
                                           pk2h(__float2half(y5.z), __float2half(y5.w)));
                    *(uint2*)(dsm + ae) = pk5;
                }
            }
        }
    }
    if (WSEL==1 && s==6){
        sdErr[tid] = errsum;
        __syncthreads();
        for (int o=256; o>0; o>>=1){
            if (tid < o) sdErr[tid] += sdErr[tid+o];
            __syncthreads();
        }
        if (tid==0) g_part[tile] = sdErr[0];
    }
}

// ============ the single persistent kernel ============
__global__ __launch_bounds__(NTHREADS,1)
void k_solver(const float* __restrict__ x,
              const float* __restrict__ w1, const float* __restrict__ b1,
              const float* __restrict__ w2, const float* __restrict__ b2,
              float* __restrict__ out)
{
    extern __shared__ __align__(16) char dsm[];
    __shared__ double sd[NTHREADS];
    const uint32_t sb = smem_u32(dsm);
    const int bid = blockIdx.x, tid = threadIdx.x;
    const int gt = bid*NTHREADS + tid;
    const int gstride = GRID*NTHREADS;

    // ---- prep: weights (transposed fp16) ----
    for (int i=gt; i<2*NWB; i+=gstride){
        int conv = i / NWB, r = i % NWB;
        int tap = r >> 14, co = (r >> 7) & 127, ci = r & 127;
        float v = (conv ? w2 : w1)[(tap*129 + ci)*128 + co];
        g_wh[conv][r] = __float2half(v);
    }
    // ---- prep: t-channel weight sums per border category ----
    if (bid==0 && tid<256){
        int conv = tid >> 7, co = tid & 127;
        const float* w = conv ? w2 : w1;
        for (int cat=0; cat<9; cat++){
            int hc = cat/3, wc = cat%3;
            float ssum = 0.f;
            for (int tap=0; tap<9; tap++){
                int dh = tap/3 - 1, dw = tap%3 - 1;
                bool okh = !((hc==0 && dh<0) || (hc==2 && dh>0));
                bool okw = !((wc==0 && dw<0) || (wc==2 && dw>0));
                if (okh && okw) ssum += w[(tap*129 + 128)*128 + co];
            }
            g_tw[conv][cat][co] = ssum;
        }
    }
    // ---- init y + phase counters ----
    if (gt < NTILE) g_pc[gt] = 0u;
    for (int q=gt; q<NQ; q+=gstride){
        float4 v = ((const float4*)x)[q];
        ((float4*)g_yf[0])[q] = v;
        h_store4(g_yh[0], q*4, v);
    }
    __syncthreads();
    prefetch_w01(sb, g_wh[0], tid);    // W0,W1 for the very first conv1
    gsync();

    // ---- per-CTA solver state (identical in every CTA) ----
    float t = 0.f, dt = 0.05f;
    int cur = 0, done = 0, reuseA = 0;
    unsigned P = 0;
    const float TC[7] = {0.f, 0.2f, 0.3f, 0.8f, (float)(8.0/9.0), 1.f, 1.f};

    for (int it=0; it<MAX_STEPS; ++it){
        if (done) break;
        const float dtc = fminf(dt, 1.0f - t);
        for (int s=0; s<7; ++s){
            const float tval = t + TC[s]*dtc;
            nb_wait(bid, P);
            conv_phase<0>(dsm, sb, bid, s, b1, dtc, tval, cur, sd, (s==0 && !reuseA));   // h
            publish(bid, P+1);
            prefetch_w01(sb, g_wh[1], tid);     // conv2's W0,W1 stream during wait
            nb_wait(bid, P+1);
            conv_phase<1>(dsm, sb, bid, s, b2, dtc, tval, cur, sd, 0);      // k_s (+fused)
            publish(bid, P+2);
            prefetch_w01(sb, g_wh[0], tid);     // next conv1's W0,W1
            P += 2;
        }
        gsync();                                // global: err partials + y commit
        // ---- controller, computed redundantly & identically in every CTA ----
        {
            double v=0.0;
            for (int i=tid; i<NTILE; i+=NTHREADS) v += __ldcg(&g_part[i]);
            sd[tid]=v; __syncthreads();
            for (int o=256; o>0; o>>=1){ if (tid<o) sd[tid]+=sd[tid+o]; __syncthreads(); }
            float err_norm = sqrtf((float)(sd[0] / (double)NTOT));
            __syncthreads();
            err_norm = fmaxf(err_norm, 1e-10f);
            int accept = (err_norm <= 1.0f) ? 1 : 0;
            float factor = 0.9f * powf(err_norm, -0.2f);
            factor = fminf(fmaxf(factor, 0.2f), 10.0f);
            if (accept){ t += dtc; cur ^= 1; }
            dt = dtc * factor;
            reuseA = accept;                    // A buffer holds y5h == new y on accept
            if (t >= 1.0f - 1e-6f) done = 1;
        }
    }

    // ---- final copy ----
    for (int q=gt; q<NQ; q+=gstride)
        ((float4*)out)[q] = __ldcg((const float4*)g_yf[cur] + q);
}

// ============ launch ============
extern "C" void kernel_launch(void* const* d_in, const int* in_sizes, int n_in,
                              void* d_out, int out_size){
    const float* x = 0; const float* w[2] = {0,0}; const float* b[2] = {0,0};
    int nw=0, nb_=0;
    for (int i=0;i<n_in;i++){
        if (in_sizes[i] == NTOT) x = (const float*)d_in[i];
        else if (in_sizes[i] == WSIZE){ if (nw<2) w[nw++] = (const float*)d_in[i]; }
        else if (in_sizes[i] == CH){ if (nb_<2) b[nb_++] = (const float*)d_in[i]; }
    }
    cudaFuncSetAttribute(k_solver, cudaFuncAttributeMaxDynamicSharedMemorySize, CONV_SMEM);
    cudaFuncSetAttribute(k_solver, cudaFuncAttributePreferredSharedMemoryCarveout, 100);
    k_solver<<<GRID, NTHREADS, CONV_SMEM>>>(x, w[0], b[0], w[1], b[1], (float*)d_out);
}